// round 13
// baseline (speedup 1.0000x reference)
#include <cuda_runtime.h>
#include <cuda_bf16.h>
#include <mma.h>
#include <math.h>
#include <float.h>
#include <stdint.h>

using namespace nvcuda;

#define Bc 2
#define Lc 1024
#define Dc 1024
#define Hc 16
#define NL 8
#define Vc 32000
#define Fc 4096
#define DHc 64

// ---------------------------------------------------------------------------
// Device-global scratch
// ---------------------------------------------------------------------------
__device__ float g_y[Bc*Lc*Dc];
__device__ float g_qkv[Bc*Lc*3*Dc];
__device__ float g_part[2*Bc*Lc*Dc];     // split-K partial buffers
__device__ float g_gp[Bc*Lc*2*Fc];
// bf16 hi/lo planes
__device__ __nv_bfloat16 g_xh[Bc*Lc*Dc],  g_xl[Bc*Lc*Dc];
__device__ __nv_bfloat16 g_qh[Bc*Lc*Dc],  g_ql[Bc*Lc*Dc];
__device__ __nv_bfloat16 g_kh[Bc*Lc*Dc],  g_kl[Bc*Lc*Dc];
__device__ __nv_bfloat16 g_vth[Bc*Hc*DHc*Lc], g_vtl[Bc*Hc*DHc*Lc];
__device__ __nv_bfloat16 g_th[Bc*Lc*Dc],  g_tl[Bc*Lc*Dc];
__device__ __nv_bfloat16 g_gh[Bc*Lc*Fc],  g_gl[Bc*Lc*Fc];
__device__ __nv_bfloat16 g_wh[166985728], g_wl[166985728];

__device__ __forceinline__ uint32_t packf(float v) {
    __nv_bfloat16 h = __float2bfloat16(v);
    float hf = __bfloat162float(h);
    __nv_bfloat16 l = __float2bfloat16(v - hf);
    return (uint32_t)__bfloat16_as_ushort(h) | ((uint32_t)__bfloat16_as_ushort(l) << 16);
}
__device__ __forceinline__ void packf2(float v, __nv_bfloat16& h, __nv_bfloat16& l) {
    h = __float2bfloat16(v);
    l = __float2bfloat16(v - __bfloat162float(h));
}

__device__ __forceinline__ uint32_t smem_u32(const void* p) {
    uint32_t a;
    asm("{ .reg .u64 t; cvta.to.shared.u64 t, %1; cvt.u32.u64 %0, t; }" : "=r"(a) : "l"(p));
    return a;
}
__device__ __forceinline__ void cpasync16(uint32_t dst, const void* src) {
    asm volatile("cp.async.cg.shared.global [%0], [%1], 16;" :: "r"(dst), "l"(src) : "memory");
}
__device__ __forceinline__ void cp_commit() {
    asm volatile("cp.async.commit_group;" ::: "memory");
}
__device__ __forceinline__ void cp_wait1() {
    asm volatile("cp.async.wait_group 1;" ::: "memory");
}
__device__ __forceinline__ void cp_wait0() {
    asm volatile("cp.async.wait_group 0;" ::: "memory");
}

// ---------------------------------------------------------------------------
// Block reductions (blockDim.x == 256)
// ---------------------------------------------------------------------------
__device__ __forceinline__ float blockReduceSum(float v) {
    __shared__ float sh[33];
    int lane = threadIdx.x & 31, wid = threadIdx.x >> 5;
    #pragma unroll
    for (int o = 16; o > 0; o >>= 1) v += __shfl_down_sync(0xffffffffu, v, o);
    if (lane == 0) sh[wid] = v;
    __syncthreads();
    v = (threadIdx.x < 8) ? sh[lane] : 0.0f;
    if (wid == 0) {
        #pragma unroll
        for (int o = 4; o > 0; o >>= 1) v += __shfl_down_sync(0xffffffffu, v, o);
        if (lane == 0) sh[32] = v;
    }
    __syncthreads();
    return sh[32];
}

// ---------------------------------------------------------------------------
// WMMA GEMM (identical to R10 core)
// ---------------------------------------------------------------------------
#define LDS_ 40

template<int BN>
__global__ __launch_bounds__(128, 2) void gemm_mma(
    const __nv_bfloat16* __restrict__ Ahp, const __nv_bfloat16* __restrict__ Alp,
    const __nv_bfloat16* __restrict__ Bhp, const __nv_bfloat16* __restrict__ Blp,
    float* __restrict__ C, __nv_bfloat16* __restrict__ Ch, __nv_bfloat16* __restrict__ Cl,
    const float* __restrict__ R,
    int K, int lda, int ldb, int ldc, int bH,
    long sAb, long sAh, long sBb, long sBh, long sCb, long sCh, int flags)
{
    const int BM = 128;
    const int WN = BN / 2;
    const int NT = WN / 16;
    const int APB = 5120;
    const int BPB = BN * LDS_;
    const int SSZ = (2 * APB + 2 * BPB) * 2;

    int row0 = blockIdx.y * BM, col0 = blockIdx.x * BN;
    if ((flags & 2) && col0 >= row0 + BM) return;
    if (flags & 4) { int kc = row0 + BM; if (kc < K) K = kc; }
    int z = blockIdx.z, zb = z / bH, zh = z - zb * bH;
    long aoff = (long)zb * sAb + (long)zh * sAh;
    long boff = (long)zb * sBb + (long)zh * sBh;
    long coff = (long)zb * sCb + (long)zh * sCh;

    extern __shared__ __align__(16) char smraw[];
    uint32_t sbase = smem_u32(smraw);

    int tid = threadIdx.x, wid = tid >> 5, lane = tid & 31;
    int wm = wid & 1, wn = wid >> 1;

    wmma::fragment<wmma::accumulator, 16, 16, 16, float> acc[4][NT];
    if (R) {
        const float* Rb = R + coff;
        #pragma unroll
        for (int i = 0; i < 4; i++)
            #pragma unroll
            for (int j = 0; j < NT; j++)
                wmma::load_matrix_sync(acc[i][j],
                    Rb + (long)(row0 + wm * 64 + i * 16) * ldc + col0 + wn * WN + j * 16,
                    ldc, wmma::mem_row_major);
    } else {
        #pragma unroll
        for (int i = 0; i < 4; i++)
            #pragma unroll
            for (int j = 0; j < NT; j++)
                wmma::fill_fragment(acc[i][j], 0.0f);
    }

    const __nv_bfloat16* Ahg = Ahp + aoff + (long)row0 * lda;
    const __nv_bfloat16* Alg = Alp + aoff + (long)row0 * lda;
    const __nv_bfloat16* Bhg = Bhp + boff + (long)col0 * ldb;
    const __nv_bfloat16* Blg = Blp + boff + (long)col0 * ldb;
    int NC = K >> 5;

    auto issue = [&](int c) {
        uint32_t sb = sbase + (c & 1) * SSZ;
        int kc = c << 5;
        #pragma unroll
        for (int i = 0; i < 4; i++) {
            int lin = tid + i * 128;
            int r = lin >> 2, g = lin & 3;
            long go = (long)r * lda + kc + g * 8;
            uint32_t so = r * 80 + g * 16;
            cpasync16(sb + so, Ahg + go);
            cpasync16(sb + 2 * APB + so, Alg + go);
        }
        #pragma unroll
        for (int i = 0; i < BN / 32; i++) {
            int lin = tid + i * 128;
            int r = lin >> 2, g = lin & 3;
            long go = (long)r * ldb + kc + g * 8;
            uint32_t so = r * 80 + g * 16;
            cpasync16(sb + 4 * APB + so, Bhg + go);
            cpasync16(sb + 4 * APB + 2 * BPB + so, Blg + go);
        }
    };

    issue(0); cp_commit();
    if (NC > 1) issue(1);
    cp_commit();

    for (int c = 0; c < NC; c++) {
        cp_wait1();
        __syncthreads();
        {
            const __nv_bfloat16* base = (const __nv_bfloat16*)(smraw + (c & 1) * SSZ);
            const __nv_bfloat16* Ah = base;
            const __nv_bfloat16* Al = base + APB;
            const __nv_bfloat16* Bh = base + 2 * APB;
            const __nv_bfloat16* Bl = base + 2 * APB + BPB;
            #pragma unroll
            for (int ks = 0; ks < 2; ks++) {
                int k0 = ks * 16;
                wmma::fragment<wmma::matrix_b, 16, 16, 16, __nv_bfloat16, wmma::col_major> fbh[NT], fbl[NT];
                #pragma unroll
                for (int j = 0; j < NT; j++) {
                    wmma::load_matrix_sync(fbh[j], Bh + (wn * WN + j * 16) * LDS_ + k0, LDS_);
                    wmma::load_matrix_sync(fbl[j], Bl + (wn * WN + j * 16) * LDS_ + k0, LDS_);
                }
                #pragma unroll
                for (int i = 0; i < 4; i++) {
                    wmma::fragment<wmma::matrix_a, 16, 16, 16, __nv_bfloat16, wmma::row_major> fah, fal;
                    wmma::load_matrix_sync(fah, Ah + (wm * 64 + i * 16) * LDS_ + k0, LDS_);
                    wmma::load_matrix_sync(fal, Al + (wm * 64 + i * 16) * LDS_ + k0, LDS_);
                    #pragma unroll
                    for (int j = 0; j < NT; j++) {
                        wmma::mma_sync(acc[i][j], fah, fbh[j], acc[i][j]);
                        wmma::mma_sync(acc[i][j], fah, fbl[j], acc[i][j]);
                        wmma::mma_sync(acc[i][j], fal, fbh[j], acc[i][j]);
                    }
                }
            }
        }
        __syncthreads();
        if (c + 2 < NC) issue(c + 2);
        cp_commit();
    }

    if (!Ch) {
        float* Cb = C + coff;
        #pragma unroll
        for (int i = 0; i < 4; i++)
            #pragma unroll
            for (int j = 0; j < NT; j++)
                wmma::store_matrix_sync(
                    Cb + (long)(row0 + wm * 64 + i * 16) * ldc + col0 + wn * WN + j * 16,
                    acc[i][j], ldc, wmma::mem_row_major);
    } else {
        __syncthreads();
        float* wbuf = (float*)smraw + wid * 256;
        #pragma unroll
        for (int i = 0; i < 4; i++)
            #pragma unroll
            for (int j = 0; j < NT; j++) {
                wmma::store_matrix_sync(wbuf, acc[i][j], 16, wmma::mem_row_major);
                __syncwarp();
                int r = lane >> 1, chn = lane & 1;
                const float* src = wbuf + r * 16 + chn * 8;
                __nv_bfloat16 hb[8], lb[8];
                #pragma unroll
                for (int t = 0; t < 8; t++) packf2(src[t], hb[t], lb[t]);
                long off = (long)(row0 + wm * 64 + i * 16 + r) * ldc + col0 + wn * WN + j * 16 + chn * 8 + coff;
                *(uint4*)(Ch + off) = *(uint4*)hb;
                *(uint4*)(Cl + off) = *(uint4*)lb;
                __syncwarp();
            }
    }
}

// ---------------------------------------------------------------------------
// Fused causal attention: per CTA = (bh, 128-row q block).
// Pass 1: hi-only QK^T -> row max (shift-invariant, approx max is exact math).
// Pass 2: full bf16x3 S, P = expf(S - max) packed hi/lo in smem, O += P*V.
// All staging through smem; O accumulated in wmma fragments.
// ---------------------------------------------------------------------------
#define QLD 72
#define VLD 136
#define SLD 132
#define PLD 136
// smem offsets (bytes)
#define OFF_QH 0
#define OFF_QL 18432
#define OFF_KH 36864
#define OFF_KL 55296
#define OFF_S  73728
#define OFF_PH 141312
#define OFF_PL 176128
#define OFF_MX 210944
#define OFF_SU 211456
#define SMEMA  211968

__global__ __launch_bounds__(256, 1) void attn_fused(
    const __nv_bfloat16* __restrict__ qh, const __nv_bfloat16* __restrict__ ql,
    const __nv_bfloat16* __restrict__ kh, const __nv_bfloat16* __restrict__ kl,
    const __nv_bfloat16* __restrict__ vth, const __nv_bfloat16* __restrict__ vtl,
    __nv_bfloat16* __restrict__ th, __nv_bfloat16* __restrict__ tl)
{
    extern __shared__ __align__(16) char sm[];
    __nv_bfloat16* Qh = (__nv_bfloat16*)(sm + OFF_QH);
    __nv_bfloat16* Ql = (__nv_bfloat16*)(sm + OFF_QL);
    __nv_bfloat16* Kh = (__nv_bfloat16*)(sm + OFF_KH);
    __nv_bfloat16* Kl = (__nv_bfloat16*)(sm + OFF_KL);
    __nv_bfloat16* Vh = (__nv_bfloat16*)(sm + OFF_KH);   // V tiles reuse K buffer
    __nv_bfloat16* Vl = (__nv_bfloat16*)(sm + OFF_KL);
    float* S  = (float*)(sm + OFF_S);
    __nv_bfloat16* Ph = (__nv_bfloat16*)(sm + OFF_PH);
    __nv_bfloat16* Pl = (__nv_bfloat16*)(sm + OFF_PL);
    float* rmax = (float*)(sm + OFF_MX);
    float* rsum = (float*)(sm + OFF_SU);

    int bh = blockIdx.y, b = bh >> 4, h = bh & 15;
    int qb = (int)gridDim.x - 1 - blockIdx.x;     // heavy blocks first
    int row0 = qb * 128;
    int tid = threadIdx.x, wid = tid >> 5;
    int wmS = wid & 3, wnS = wid >> 2;            // S: 32x64 per warp
    int wmO = wid & 3, wnO = wid >> 2;            // O: 32x32 per warp

    uint32_t sQh = smem_u32(Qh), sQl = smem_u32(Ql);
    uint32_t sKh = smem_u32(Kh), sKl = smem_u32(Kl);
    uint32_t sVh = sKh, sVl = sKl;

    const __nv_bfloat16* qhg = qh + ((long)(b * Lc + row0)) * Dc + h * DHc;
    const __nv_bfloat16* qlg = ql + ((long)(b * Lc + row0)) * Dc + h * DHc;
    #pragma unroll
    for (int i = 0; i < 4; i++) {
        int lin = tid + i * 256; int r = lin >> 3; int c = (lin & 7) * 8;
        cpasync16(sQh + (uint32_t)(r * QLD + c) * 2, qhg + (long)r * Dc + c);
        cpasync16(sQl + (uint32_t)(r * QLD + c) * 2, qlg + (long)r * Dc + c);
    }
    cp_commit(); cp_wait0();
    if (tid < 128) { rmax[tid] = -FLT_MAX; rsum[tid] = 0.0f; }
    __syncthreads();

    // ---- pass 1: hi-only scores -> row max ----
    for (int j = 0; j <= qb; j++) {
        const __nv_bfloat16* khg = kh + ((long)(b * Lc + j * 128)) * Dc + h * DHc;
        #pragma unroll
        for (int i = 0; i < 4; i++) {
            int lin = tid + i * 256; int r = lin >> 3; int c = (lin & 7) * 8;
            cpasync16(sKh + (uint32_t)(r * QLD + c) * 2, khg + (long)r * Dc + c);
        }
        cp_commit(); cp_wait0();
        __syncthreads();
        wmma::fragment<wmma::accumulator, 16, 16, 16, float> sa[2][4];
        #pragma unroll
        for (int i = 0; i < 2; i++)
            #pragma unroll
            for (int jj = 0; jj < 4; jj++) wmma::fill_fragment(sa[i][jj], 0.0f);
        #pragma unroll
        for (int ks = 0; ks < 4; ks++) {
            int k0 = ks * 16;
            wmma::fragment<wmma::matrix_a, 16, 16, 16, __nv_bfloat16, wmma::row_major> fa[2];
            #pragma unroll
            for (int i = 0; i < 2; i++)
                wmma::load_matrix_sync(fa[i], Qh + (wmS * 32 + i * 16) * QLD + k0, QLD);
            #pragma unroll
            for (int jj = 0; jj < 4; jj++) {
                wmma::fragment<wmma::matrix_b, 16, 16, 16, __nv_bfloat16, wmma::col_major> fb;
                wmma::load_matrix_sync(fb, Kh + (wnS * 64 + jj * 16) * QLD + k0, QLD);
                #pragma unroll
                for (int i = 0; i < 2; i++) wmma::mma_sync(sa[i][jj], fa[i], fb, sa[i][jj]);
            }
        }
        #pragma unroll
        for (int i = 0; i < 2; i++)
            #pragma unroll
            for (int jj = 0; jj < 4; jj++)
                wmma::store_matrix_sync(S + (wmS * 32 + i * 16) * SLD + wnS * 64 + jj * 16,
                                        sa[i][jj], SLD, wmma::mem_row_major);
        __syncthreads();
        {
            int r = tid >> 1, c0 = (tid & 1) * 64;
            int lim = (j < qb) ? 64 : (r - c0 + 1);
            if (lim > 64) lim = 64;
            float m = -FLT_MAX;
            for (int c = 0; c < lim; c++) m = fmaxf(m, S[r * SLD + c0 + c]);
            float mo = __shfl_xor_sync(0xffffffffu, m, 1);
            m = fmaxf(m, mo);
            if ((tid & 1) == 0) rmax[r] = fmaxf(rmax[r], m);
        }
        __syncthreads();
    }

    // ---- pass 2: full scores, P, O accumulation ----
    wmma::fragment<wmma::accumulator, 16, 16, 16, float> oa[2][2];
    #pragma unroll
    for (int i = 0; i < 2; i++)
        #pragma unroll
        for (int jj = 0; jj < 2; jj++) wmma::fill_fragment(oa[i][jj], 0.0f);

    for (int j = 0; j <= qb; j++) {
        __syncthreads();   // protect K/V buffer from previous AV reads
        const __nv_bfloat16* khg = kh + ((long)(b * Lc + j * 128)) * Dc + h * DHc;
        const __nv_bfloat16* klg = kl + ((long)(b * Lc + j * 128)) * Dc + h * DHc;
        #pragma unroll
        for (int i = 0; i < 4; i++) {
            int lin = tid + i * 256; int r = lin >> 3; int c = (lin & 7) * 8;
            cpasync16(sKh + (uint32_t)(r * QLD + c) * 2, khg + (long)r * Dc + c);
            cpasync16(sKl + (uint32_t)(r * QLD + c) * 2, klg + (long)r * Dc + c);
        }
        cp_commit(); cp_wait0();
        __syncthreads();
        {
            wmma::fragment<wmma::accumulator, 16, 16, 16, float> sa[2][4];
            #pragma unroll
            for (int i = 0; i < 2; i++)
                #pragma unroll
                for (int jj = 0; jj < 4; jj++) wmma::fill_fragment(sa[i][jj], 0.0f);
            #pragma unroll
            for (int ks = 0; ks < 4; ks++) {
                int k0 = ks * 16;
                wmma::fragment<wmma::matrix_a, 16, 16, 16, __nv_bfloat16, wmma::row_major> fah[2], fal[2];
                #pragma unroll
                for (int i = 0; i < 2; i++) {
                    wmma::load_matrix_sync(fah[i], Qh + (wmS * 32 + i * 16) * QLD + k0, QLD);
                    wmma::load_matrix_sync(fal[i], Ql + (wmS * 32 + i * 16) * QLD + k0, QLD);
                }
                #pragma unroll
                for (int jj = 0; jj < 4; jj++) {
                    wmma::fragment<wmma::matrix_b, 16, 16, 16, __nv_bfloat16, wmma::col_major> fbh, fbl;
                    wmma::load_matrix_sync(fbh, Kh + (wnS * 64 + jj * 16) * QLD + k0, QLD);
                    wmma::load_matrix_sync(fbl, Kl + (wnS * 64 + jj * 16) * QLD + k0, QLD);
                    #pragma unroll
                    for (int i = 0; i < 2; i++) {
                        wmma::mma_sync(sa[i][jj], fah[i], fbh, sa[i][jj]);
                        wmma::mma_sync(sa[i][jj], fah[i], fbl, sa[i][jj]);
                        wmma::mma_sync(sa[i][jj], fal[i], fbh, sa[i][jj]);
                    }
                }
            }
            #pragma unroll
            for (int i = 0; i < 2; i++)
                #pragma unroll
                for (int jj = 0; jj < 4; jj++)
                    wmma::store_matrix_sync(S + (wmS * 32 + i * 16) * SLD + wnS * 64 + jj * 16,
                                            sa[i][jj], SLD, wmma::mem_row_major);
        }
        __syncthreads();
        // V tile loads (reuse K buffer; S gemm done) overlapped with P compute
        const __nv_bfloat16* vhg = vth + (long)bh * DHc * Lc + j * 128;
        const __nv_bfloat16* vlg = vtl + (long)bh * DHc * Lc + j * 128;
        #pragma unroll
        for (int i = 0; i < 4; i++) {
            int lin = tid + i * 256; int d = lin >> 4; int c = (lin & 15) * 8;
            cpasync16(sVh + (uint32_t)(d * VLD + c) * 2, vhg + (long)d * Lc + c);
            cpasync16(sVl + (uint32_t)(d * VLD + c) * 2, vlg + (long)d * Lc + c);
        }
        cp_commit();
        {
            int r = tid >> 1, c0 = (tid & 1) * 64;
            float m = rmax[r]; float ls = 0.0f;
            int lim = (j < qb) ? 64 : (r - c0 + 1);
            if (lim > 64) lim = 64;
            if (lim < 0) lim = 0;
            for (int c = 0; c < 64; c++) {
                float p = 0.0f;
                if (c < lim) { p = __expf(S[r * SLD + c0 + c] - m); ls += p; }
                __nv_bfloat16 hbv, lbv; packf2(p, hbv, lbv);
                Ph[r * PLD + c0 + c] = hbv; Pl[r * PLD + c0 + c] = lbv;
            }
            float lo = __shfl_xor_sync(0xffffffffu, ls, 1);
            ls += lo;
            if ((tid & 1) == 0) rsum[r] += ls;
        }
        cp_wait0();
        __syncthreads();
        // O += P * V
        #pragma unroll
        for (int ks = 0; ks < 8; ks++) {
            int k0 = ks * 16;
            wmma::fragment<wmma::matrix_a, 16, 16, 16, __nv_bfloat16, wmma::row_major> pah[2], pal[2];
            #pragma unroll
            for (int i = 0; i < 2; i++) {
                wmma::load_matrix_sync(pah[i], Ph + (wmO * 32 + i * 16) * PLD + k0, PLD);
                wmma::load_matrix_sync(pal[i], Pl + (wmO * 32 + i * 16) * PLD + k0, PLD);
            }
            #pragma unroll
            for (int jj = 0; jj < 2; jj++) {
                wmma::fragment<wmma::matrix_b, 16, 16, 16, __nv_bfloat16, wmma::col_major> vbh, vbl;
                wmma::load_matrix_sync(vbh, Vh + (wnO * 32 + jj * 16) * VLD + k0, VLD);
                wmma::load_matrix_sync(vbl, Vl + (wnO * 32 + jj * 16) * VLD + k0, VLD);
                #pragma unroll
                for (int i = 0; i < 2; i++) {
                    wmma::mma_sync(oa[i][jj], pah[i], vbh, oa[i][jj]);
                    wmma::mma_sync(oa[i][jj], pah[i], vbl, oa[i][jj]);
                    wmma::mma_sync(oa[i][jj], pal[i], vbh, oa[i][jj]);
                }
            }
        }
    }
    __syncthreads();
    #pragma unroll
    for (int i = 0; i < 2; i++)
        #pragma unroll
        for (int jj = 0; jj < 2; jj++)
            wmma::store_matrix_sync(S + (wmO * 32 + i * 16) * SLD + wnO * 32 + jj * 16,
                                    oa[i][jj], SLD, wmma::mem_row_major);
    __syncthreads();
    {
        int r = tid >> 1, c0 = (tid & 1) * 32;
        float inv = 1.0f / rsum[r];
        long ob = ((long)(b * Lc + row0 + r)) * Dc + h * DHc + c0;
        #pragma unroll
        for (int c = 0; c < 32; c++) {
            __nv_bfloat16 hbv, lbv;
            packf2(S[r * SLD + c0 + c] * inv, hbv, lbv);
            th[ob + c] = hbv; tl[ob + c] = lbv;
        }
    }
}

// ---------------------------------------------------------------------------
// Split-K reduction
// ---------------------------------------------------------------------------
__global__ void reduce_k(float* __restrict__ y, const float* __restrict__ p0,
                         const float* __restrict__ p1) {
    int i = blockIdx.x * 256 + threadIdx.x;
    float4 a = ((const float4*)y)[i];
    float4 b = ((const float4*)p0)[i];
    float4 c = ((const float4*)p1)[i];
    a.x += b.x + c.x; a.y += b.y + c.y; a.z += b.z + c.z; a.w += b.w + c.w;
    ((float4*)y)[i] = a;
}

// ---------------------------------------------------------------------------
// Aux kernels
// ---------------------------------------------------------------------------
__global__ void embed_k(const int* __restrict__ tokens, const float* __restrict__ emb,
                        float* __restrict__ y) {
    int r = blockIdx.x;
    int tok = tokens[r];
    const float4* src = (const float4*)(emb + (long)tok * Dc);
    float4* dst = (float4*)(y + (long)r * Dc);
    for (int i = threadIdx.x; i < Dc / 4; i += blockDim.x) dst[i] = src[i];
}

__global__ void rmsnorm_pack(const float* __restrict__ in, const float* __restrict__ w,
                             __nv_bfloat16* __restrict__ oh, __nv_bfloat16* __restrict__ ol) {
    long b = (long)blockIdx.x * Dc;
    float s = 0.0f;
    for (int i = threadIdx.x; i < Dc; i += 256) { float v = in[b + i]; s += v * v; }
    s = blockReduceSum(s);
    float inv = rsqrtf(s * (1.0f / Dc) + 1e-6f);
    for (int i = threadIdx.x; i < Dc; i += 256)
        packf2(in[b + i] * inv * w[i], oh[b + i], ol[b + i]);
}

__global__ void rope_pack(const float* __restrict__ qkv,
                          __nv_bfloat16* __restrict__ qh, __nv_bfloat16* __restrict__ ql,
                          __nv_bfloat16* __restrict__ kh, __nv_bfloat16* __restrict__ kl) {
    int idx = blockIdx.x * 256 + threadIdx.x;
    int i = idx & 31;
    int rest = idx >> 5;
    int h = rest & (Hc - 1);
    int rl = rest >> 4;
    int l = rl & (Lc - 1);
    float ts_inv = expf((float)i * -0.28782313662425572f);
    float ang = (float)l * ts_inv;
    float sn, cs;
    sincosf(ang, &sn, &cs);
    long src = (long)rl * 3072 + h * DHc + i;
    long dst = (long)rl * Dc + h * DHc + i;
    float q1 = qkv[src], q2 = qkv[src + 32];
    packf2((q1 * cs - q2 * sn) * 0.125f, qh[dst], ql[dst]);
    packf2((q2 * cs + q1 * sn) * 0.125f, qh[dst + 32], ql[dst + 32]);
    float k1 = qkv[src + 1024], k2 = qkv[src + 1024 + 32];
    packf2(k1 * cs - k2 * sn, kh[dst], kl[dst]);
    packf2(k2 * cs + k1 * sn, kh[dst + 32], kl[dst + 32]);
}

__global__ void vtrans_pack(const float* __restrict__ qkv,
                            __nv_bfloat16* __restrict__ vh, __nv_bfloat16* __restrict__ vl) {
    __shared__ uint32_t t[32][33];
    int bh = blockIdx.z; int b = bh >> 4, h = bh & 15;
    int l0 = blockIdx.x * 32, d0 = blockIdx.y * 32;
    int tx = threadIdx.x, ty = threadIdx.y;
    float val = qkv[(long)(b * Lc + l0 + ty) * 3072 + 2048 + h * DHc + d0 + tx];
    t[ty][tx] = packf(val);
    __syncthreads();
    uint32_t p = t[tx][ty];
    long o = ((long)bh * DHc + d0 + ty) * Lc + l0 + tx;
    vh[o] = __ushort_as_bfloat16((unsigned short)(p & 0xFFFF));
    vl[o] = __ushort_as_bfloat16((unsigned short)(p >> 16));
}

__global__ void swish_pack(const float* __restrict__ gp,
                           __nv_bfloat16* __restrict__ oh, __nv_bfloat16* __restrict__ ol) {
    int i = blockIdx.x * 256 + threadIdx.x;
    int row = i >> 12, col = i & 4095;
    float gv = gp[(long)row * 8192 + col];
    float pv = gp[(long)row * 8192 + 4096 + col];
    float sw = gv / (1.0f + __expf(-gv)) * pv;
    packf2(sw, oh[i], ol[i]);
}

__global__ void wtrans(const float* __restrict__ W,
                       __nv_bfloat16* __restrict__ Oh, __nv_bfloat16* __restrict__ Ol,
                       int Kd, int Nd, long ostride) {
    __shared__ uint32_t t[32][33];
    long li = (long)blockIdx.z * Kd * Nd;
    long lo_ = (long)blockIdx.z * ostride;
    int n0 = blockIdx.x * 32, k0 = blockIdx.y * 32;
    int tx = threadIdx.x;
    int ty = threadIdx.y;
    float4 v = *(const float4*)(W + li + (long)(k0 + ty) * Nd + n0 + tx * 4);
    t[tx * 4 + 0][ty] = packf(v.x);
    t[tx * 4 + 1][ty] = packf(v.y);
    t[tx * 4 + 2][ty] = packf(v.z);
    t[tx * 4 + 3][ty] = packf(v.w);
    __syncthreads();
    uint32_t p0 = t[ty][tx * 4], p1 = t[ty][tx * 4 + 1], p2 = t[ty][tx * 4 + 2], p3 = t[ty][tx * 4 + 3];
    ushort4 hs = make_ushort4((unsigned short)(p0 & 0xFFFF), (unsigned short)(p1 & 0xFFFF),
                              (unsigned short)(p2 & 0xFFFF), (unsigned short)(p3 & 0xFFFF));
    ushort4 ls = make_ushort4((unsigned short)(p0 >> 16), (unsigned short)(p1 >> 16),
                              (unsigned short)(p2 >> 16), (unsigned short)(p3 >> 16));
    long o = lo_ + (long)(n0 + ty) * Kd + k0 + tx * 4;
    *(ushort4*)(Oh + o) = hs;
    *(ushort4*)(Ol + o) = ls;
}

// ---------------------------------------------------------------------------
// Host
// ---------------------------------------------------------------------------
#define SM128 (2 * (20480 + 128 * 160))   // 81920

extern "C" void kernel_launch(void* const* d_in, const int* in_sizes, int n_in,
                              void* d_out, int out_size) {
    const int*   tokens = (const int*)d_in[0];
    const float* embed  = (const float*)d_in[1];
    const float* ln1    = (const float*)d_in[2];
    const float* Wq     = (const float*)d_in[3];
    const float* Wk     = (const float*)d_in[4];
    const float* Wv     = (const float*)d_in[5];
    const float* Wo     = (const float*)d_in[6];
    const float* ln2    = (const float*)d_in[7];
    const float* Wg     = (const float*)d_in[8];
    const float* Wp     = (const float*)d_in[9];
    const float* Wd     = (const float*)d_in[10];
    const float* out_ln = (const float*)d_in[11];
    const float* head   = (const float*)d_in[12];

    cudaFuncSetAttribute(gemm_mma<128>, cudaFuncAttributeMaxDynamicSharedMemorySize, SM128);
    cudaFuncSetAttribute(attn_fused,    cudaFuncAttributeMaxDynamicSharedMemorySize, SMEMA);

    float *y, *qkv, *part, *gp;
    __nv_bfloat16 *xh, *xl, *qh, *ql, *kh, *kl, *vth, *vtl, *th, *tl, *gh, *gl, *wh, *wl;
    cudaGetSymbolAddress((void**)&y,    g_y);
    cudaGetSymbolAddress((void**)&qkv,  g_qkv);
    cudaGetSymbolAddress((void**)&part, g_part);
    cudaGetSymbolAddress((void**)&gp,   g_gp);
    cudaGetSymbolAddress((void**)&xh,   g_xh);  cudaGetSymbolAddress((void**)&xl, g_xl);
    cudaGetSymbolAddress((void**)&qh,   g_qh);  cudaGetSymbolAddress((void**)&ql, g_ql);
    cudaGetSymbolAddress((void**)&kh,   g_kh);  cudaGetSymbolAddress((void**)&kl, g_kl);
    cudaGetSymbolAddress((void**)&vth,  g_vth); cudaGetSymbolAddress((void**)&vtl, g_vtl);
    cudaGetSymbolAddress((void**)&th,   g_th);  cudaGetSymbolAddress((void**)&tl, g_tl);
    cudaGetSymbolAddress((void**)&gh,   g_gh);  cudaGetSymbolAddress((void**)&gl, g_gl);
    cudaGetSymbolAddress((void**)&wh,   g_wh);  cudaGetSymbolAddress((void**)&wl, g_wl);

    const long OQKV = 0;
    const long OO   = 25165824;
    const long OGP  = 33554432;
    const long OD   = 100663296;
    const long OH   = 134217728;
    const long MD   = (long)Bc * Lc * Dc;

    dim3 tw(8, 32);
    wtrans<<<dim3(32, 32, 8),   tw>>>(Wq, wh + OQKV,            wl + OQKV,            1024, 1024, 3145728);
    wtrans<<<dim3(32, 32, 8),   tw>>>(Wk, wh + OQKV + 1048576,  wl + OQKV + 1048576,  1024, 1024, 3145728);
    wtrans<<<dim3(32, 32, 8),   tw>>>(Wv, wh + OQKV + 2097152,  wl + OQKV + 2097152,  1024, 1024, 3145728);
    wtrans<<<dim3(32, 32, 8),   tw>>>(Wo, wh + OO,              wl + OO,              1024, 1024, 1048576);
    wtrans<<<dim3(128, 32, 8),  tw>>>(Wg, wh + OGP,             wl + OGP,             1024, 4096, 8388608);
    wtrans<<<dim3(128, 32, 8),  tw>>>(Wp, wh + OGP + 4194304,   wl + OGP + 4194304,   1024, 4096, 8388608);
    wtrans<<<dim3(32, 128, 8),  tw>>>(Wd, wh + OD,              wl + OD,              4096, 1024, 4194304);
    wtrans<<<dim3(1000, 32, 1), tw>>>(head, wh + OH,            wl + OH,              1024, 32000, 0);

    embed_k<<<Bc * Lc, 256>>>(tokens, embed, y);

    dim3 tb(32, 32);

    for (int l = 0; l < NL; l++) {
        rmsnorm_pack<<<Bc * Lc, 256>>>(y, ln1 + (long)l * Dc, xh, xl);

        gemm_mma<128><<<dim3(24, 16, 1), 128, SM128>>>(
            xh, xl, wh + OQKV + (long)l * 3145728, wl + OQKV + (long)l * 3145728,
            qkv, 0, 0, 0, 1024, 1024, 1024, 3072, 1, 0, 0, 0, 0, 0, 0, 0);

        rope_pack<<<4096, 256>>>(qkv, qh, ql, kh, kl);
        vtrans_pack<<<dim3(32, 2, 32), tb>>>(qkv, vth, vtl);

        // fused attention: scores + softmax + AV in one kernel
        attn_fused<<<dim3(8, 32), 256, SMEMA>>>(qh, ql, kh, kl, vth, vtl, th, tl);

        gemm_mma<128><<<dim3(8, 16, 2), 128, SM128>>>(
            th, tl, wh + OO + (long)l * 1048576, wl + OO + (long)l * 1048576,
            part, 0, 0, 0, 512, 1024, 1024, 1024, 1,
            512, 0, 512, 0, MD, 0, 0);
        reduce_k<<<(int)(MD / 1024), 256>>>(y, part, part + MD);

        rmsnorm_pack<<<Bc * Lc, 256>>>(y, ln2 + (long)l * Dc, xh, xl);

        gemm_mma<128><<<dim3(64, 16, 1), 128, SM128>>>(
            xh, xl, wh + OGP + (long)l * 8388608, wl + OGP + (long)l * 8388608,
            gp, 0, 0, 0, 1024, 1024, 1024, 8192, 1, 0, 0, 0, 0, 0, 0, 0);

        swish_pack<<<32768, 256>>>(gp, gh, gl);

        gemm_mma<128><<<dim3(8, 16, 2), 128, SM128>>>(
            gh, gl, wh + OD + (long)l * 4194304, wl + OD + (long)l * 4194304,
            part, 0, 0, 0, 2048, 4096, 4096, 1024, 1,
            2048, 0, 2048, 0, MD, 0, 0);
        reduce_k<<<(int)(MD / 1024), 256>>>(y, part, part + MD);
    }

    rmsnorm_pack<<<Bc * Lc, 256>>>(y, out_ln, xh, xl);
    gemm_mma<128><<<dim3(250, 16, 1), 128, SM128>>>(
        xh, xl, wh + OH, wl + OH, (float*)d_out, 0, 0, 0,
        1024, 1024, 1024, 32000, 1, 0, 0, 0, 0, 0, 0, 0);
}

// round 14
// speedup vs baseline: 1.0627x; 1.0627x over previous
#include <cuda_runtime.h>
#include <cuda_bf16.h>
#include <mma.h>
#include <math.h>
#include <float.h>
#include <stdint.h>

using namespace nvcuda;

#define Bc 2
#define Lc 1024
#define Dc 1024
#define Hc 16
#define NL 8
#define Vc 32000
#define Fc 4096
#define DHc 64

// ---------------------------------------------------------------------------
// Device-global scratch
// ---------------------------------------------------------------------------
__device__ float g_y[Bc*Lc*Dc];
__device__ float g_qkv[Bc*Lc*3*Dc];
__device__ float g_att[Bc*Hc*Lc*Lc];     // attention scores; split-K partials alias
__device__ float g_gp[Bc*Lc*2*Fc];
// bf16 hi/lo planes
__device__ __nv_bfloat16 g_xh[Bc*Lc*Dc],  g_xl[Bc*Lc*Dc];
__device__ __nv_bfloat16 g_qh[Bc*Lc*Dc],  g_ql[Bc*Lc*Dc];
__device__ __nv_bfloat16 g_kh[Bc*Lc*Dc],  g_kl[Bc*Lc*Dc];
__device__ __nv_bfloat16 g_vth[Bc*Hc*DHc*Lc], g_vtl[Bc*Hc*DHc*Lc];
__device__ __nv_bfloat16 g_th[Bc*Lc*Dc],  g_tl[Bc*Lc*Dc];
__device__ __nv_bfloat16 g_ph[Bc*Hc*Lc*Lc], g_pl[Bc*Hc*Lc*Lc];
__device__ __nv_bfloat16 g_gh[Bc*Lc*Fc],  g_gl[Bc*Lc*Fc];
__device__ __nv_bfloat16 g_wh[166985728], g_wl[166985728];
// dedicated split-K partial buffers (att is busy until AV completes; keep separate)
__device__ float g_part[2*Bc*Lc*Dc];

__device__ __forceinline__ uint32_t packf(float v) {
    __nv_bfloat16 h = __float2bfloat16(v);
    float hf = __bfloat162float(h);
    __nv_bfloat16 l = __float2bfloat16(v - hf);
    return (uint32_t)__bfloat16_as_ushort(h) | ((uint32_t)__bfloat16_as_ushort(l) << 16);
}
__device__ __forceinline__ void packf2(float v, __nv_bfloat16& h, __nv_bfloat16& l) {
    h = __float2bfloat16(v);
    l = __float2bfloat16(v - __bfloat162float(h));
}

__device__ __forceinline__ uint32_t smem_u32(const void* p) {
    uint32_t a;
    asm("{ .reg .u64 t; cvta.to.shared.u64 t, %1; cvt.u32.u64 %0, t; }" : "=r"(a) : "l"(p));
    return a;
}
__device__ __forceinline__ void cpasync16(uint32_t dst, const void* src) {
    asm volatile("cp.async.cg.shared.global [%0], [%1], 16;" :: "r"(dst), "l"(src) : "memory");
}
__device__ __forceinline__ void cp_commit() {
    asm volatile("cp.async.commit_group;" ::: "memory");
}
__device__ __forceinline__ void cp_wait1() {
    asm volatile("cp.async.wait_group 1;" ::: "memory");
}

// ---------------------------------------------------------------------------
// Block reductions (blockDim.x == 256)
// ---------------------------------------------------------------------------
__device__ __forceinline__ float blockReduceSum(float v) {
    __shared__ float sh[33];
    int lane = threadIdx.x & 31, wid = threadIdx.x >> 5;
    #pragma unroll
    for (int o = 16; o > 0; o >>= 1) v += __shfl_down_sync(0xffffffffu, v, o);
    if (lane == 0) sh[wid] = v;
    __syncthreads();
    v = (threadIdx.x < 8) ? sh[lane] : 0.0f;
    if (wid == 0) {
        #pragma unroll
        for (int o = 4; o > 0; o >>= 1) v += __shfl_down_sync(0xffffffffu, v, o);
        if (lane == 0) sh[32] = v;
    }
    __syncthreads();
    return sh[32];
}
__device__ __forceinline__ float blockReduceMax(float v) {
    __shared__ float sh[33];
    int lane = threadIdx.x & 31, wid = threadIdx.x >> 5;
    #pragma unroll
    for (int o = 16; o > 0; o >>= 1) v = fmaxf(v, __shfl_down_sync(0xffffffffu, v, o));
    if (lane == 0) sh[wid] = v;
    __syncthreads();
    v = (threadIdx.x < 8) ? sh[lane] : -FLT_MAX;
    if (wid == 0) {
        #pragma unroll
        for (int o = 4; o > 0; o >>= 1) v = fmaxf(v, __shfl_down_sync(0xffffffffu, v, o));
        if (lane == 0) sh[32] = v;
    }
    __syncthreads();
    return sh[32];
}

// ---------------------------------------------------------------------------
// WMMA GEMM (R10 core)
// ---------------------------------------------------------------------------
#define LDS_ 40

template<int BN>
__global__ __launch_bounds__(128, 2) void gemm_mma(
    const __nv_bfloat16* __restrict__ Ahp, const __nv_bfloat16* __restrict__ Alp,
    const __nv_bfloat16* __restrict__ Bhp, const __nv_bfloat16* __restrict__ Blp,
    float* __restrict__ C, __nv_bfloat16* __restrict__ Ch, __nv_bfloat16* __restrict__ Cl,
    const float* __restrict__ R,
    int K, int lda, int ldb, int ldc, int bH,
    long sAb, long sAh, long sBb, long sBh, long sCb, long sCh, int flags)
{
    const int BM = 128;
    const int WN = BN / 2;
    const int NT = WN / 16;
    const int APB = 5120;
    const int BPB = BN * LDS_;
    const int SSZ = (2 * APB + 2 * BPB) * 2;

    int by = blockIdx.y;
    if (flags & 8) by = (by < 4) ? by : 11 - by;
    int row0 = by * BM, col0 = blockIdx.x * BN;
    if ((flags & 2) && col0 >= row0 + BM) return;
    if (flags & 4) { int kc = row0 + BM; if (kc < K) K = kc; }
    int z = blockIdx.z, zb = z / bH, zh = z - zb * bH;
    long aoff = (long)zb * sAb + (long)zh * sAh;
    long boff = (long)zb * sBb + (long)zh * sBh;
    long coff = (long)zb * sCb + (long)zh * sCh;

    extern __shared__ __align__(16) char smraw[];
    uint32_t sbase = smem_u32(smraw);

    int tid = threadIdx.x, wid = tid >> 5, lane = tid & 31;
    int wm = wid & 1, wn = wid >> 1;

    wmma::fragment<wmma::accumulator, 16, 16, 16, float> acc[4][NT];
    if (R) {
        const float* Rb = R + coff;
        #pragma unroll
        for (int i = 0; i < 4; i++)
            #pragma unroll
            for (int j = 0; j < NT; j++)
                wmma::load_matrix_sync(acc[i][j],
                    Rb + (long)(row0 + wm * 64 + i * 16) * ldc + col0 + wn * WN + j * 16,
                    ldc, wmma::mem_row_major);
    } else {
        #pragma unroll
        for (int i = 0; i < 4; i++)
            #pragma unroll
            for (int j = 0; j < NT; j++)
                wmma::fill_fragment(acc[i][j], 0.0f);
    }

    const __nv_bfloat16* Ahg = Ahp + aoff + (long)row0 * lda;
    const __nv_bfloat16* Alg = Alp + aoff + (long)row0 * lda;
    const __nv_bfloat16* Bhg = Bhp + boff + (long)col0 * ldb;
    const __nv_bfloat16* Blg = Blp + boff + (long)col0 * ldb;
    int NC = K >> 5;

    auto issue = [&](int c) {
        uint32_t sb = sbase + (c & 1) * SSZ;
        int kc = c << 5;
        #pragma unroll
        for (int i = 0; i < 4; i++) {
            int lin = tid + i * 128;
            int r = lin >> 2, g = lin & 3;
            long go = (long)r * lda + kc + g * 8;
            uint32_t so = r * 80 + g * 16;
            cpasync16(sb + so, Ahg + go);
            cpasync16(sb + 2 * APB + so, Alg + go);
        }
        #pragma unroll
        for (int i = 0; i < BN / 32; i++) {
            int lin = tid + i * 128;
            int r = lin >> 2, g = lin & 3;
            long go = (long)r * ldb + kc + g * 8;
            uint32_t so = r * 80 + g * 16;
            cpasync16(sb + 4 * APB + so, Bhg + go);
            cpasync16(sb + 4 * APB + 2 * BPB + so, Blg + go);
        }
    };

    issue(0); cp_commit();
    if (NC > 1) issue(1);
    cp_commit();

    for (int c = 0; c < NC; c++) {
        cp_wait1();
        __syncthreads();
        {
            const __nv_bfloat16* base = (const __nv_bfloat16*)(smraw + (c & 1) * SSZ);
            const __nv_bfloat16* Ah = base;
            const __nv_bfloat16* Al = base + APB;
            const __nv_bfloat16* Bh = base + 2 * APB;
            const __nv_bfloat16* Bl = base + 2 * APB + BPB;
            #pragma unroll
            for (int ks = 0; ks < 2; ks++) {
                int k0 = ks * 16;
                wmma::fragment<wmma::matrix_b, 16, 16, 16, __nv_bfloat16, wmma::col_major> fbh[NT], fbl[NT];
                #pragma unroll
                for (int j = 0; j < NT; j++) {
                    wmma::load_matrix_sync(fbh[j], Bh + (wn * WN + j * 16) * LDS_ + k0, LDS_);
                    wmma::load_matrix_sync(fbl[j], Bl + (wn * WN + j * 16) * LDS_ + k0, LDS_);
                }
                #pragma unroll
                for (int i = 0; i < 4; i++) {
                    wmma::fragment<wmma::matrix_a, 16, 16, 16, __nv_bfloat16, wmma::row_major> fah, fal;
                    wmma::load_matrix_sync(fah, Ah + (wm * 64 + i * 16) * LDS_ + k0, LDS_);
                    wmma::load_matrix_sync(fal, Al + (wm * 64 + i * 16) * LDS_ + k0, LDS_);
                    #pragma unroll
                    for (int j = 0; j < NT; j++) {
                        wmma::mma_sync(acc[i][j], fah, fbh[j], acc[i][j]);
                        wmma::mma_sync(acc[i][j], fah, fbl[j], acc[i][j]);
                        wmma::mma_sync(acc[i][j], fal, fbh[j], acc[i][j]);
                    }
                }
            }
        }
        __syncthreads();
        if (c + 2 < NC) issue(c + 2);
        cp_commit();
    }

    if (!Ch) {
        float* Cb = C + coff;
        #pragma unroll
        for (int i = 0; i < 4; i++)
            #pragma unroll
            for (int j = 0; j < NT; j++)
                wmma::store_matrix_sync(
                    Cb + (long)(row0 + wm * 64 + i * 16) * ldc + col0 + wn * WN + j * 16,
                    acc[i][j], ldc, wmma::mem_row_major);
    } else {
        __syncthreads();
        float* wbuf = (float*)smraw + wid * 256;
        #pragma unroll
        for (int i = 0; i < 4; i++)
            #pragma unroll
            for (int j = 0; j < NT; j++) {
                wmma::store_matrix_sync(wbuf, acc[i][j], 16, wmma::mem_row_major);
                __syncwarp();
                int r = lane >> 1, chn = lane & 1;
                const float* src = wbuf + r * 16 + chn * 8;
                __nv_bfloat16 hb[8], lb[8];
                #pragma unroll
                for (int t = 0; t < 8; t++) packf2(src[t], hb[t], lb[t]);
                long off = (long)(row0 + wm * 64 + i * 16 + r) * ldc + col0 + wn * WN + j * 16 + chn * 8 + coff;
                *(uint4*)(Ch + off) = *(uint4*)hb;
                *(uint4*)(Cl + off) = *(uint4*)lb;
                __syncwarp();
            }
    }
}

// ---------------------------------------------------------------------------
// Fused split-K reduce + residual + rmsnorm + pack:
//   y[row] += p0[row] + p1[row];  x = rmsnorm(y, w) -> packed hi/lo planes
// One block per row (256 threads, 4 elems/thread).
// ---------------------------------------------------------------------------
__global__ void reduce_norm_pack(float* __restrict__ y,
                                 const float* __restrict__ p0, const float* __restrict__ p1,
                                 const float* __restrict__ w,
                                 __nv_bfloat16* __restrict__ oh, __nv_bfloat16* __restrict__ ol) {
    long b = (long)blockIdx.x * Dc;
    int tid = threadIdx.x;
    float vals[4];
    float s = 0.0f;
    #pragma unroll
    for (int j = 0; j < 4; j++) {
        int i = tid + j * 256;
        float v = y[b + i] + p0[b + i] + p1[b + i];
        vals[j] = v;
        y[b + i] = v;
        s += v * v;
    }
    s = blockReduceSum(s);
    float inv = rsqrtf(s * (1.0f / Dc) + 1e-6f);
    #pragma unroll
    for (int j = 0; j < 4; j++) {
        int i = tid + j * 256;
        packf2(vals[j] * inv * w[i], oh[b + i], ol[b + i]);
    }
}

// ---------------------------------------------------------------------------
// Aux kernels
// ---------------------------------------------------------------------------
__global__ void embed_k(const int* __restrict__ tokens, const float* __restrict__ emb,
                        float* __restrict__ y) {
    int r = blockIdx.x;
    int tok = tokens[r];
    const float4* src = (const float4*)(emb + (long)tok * Dc);
    float4* dst = (float4*)(y + (long)r * Dc);
    for (int i = threadIdx.x; i < Dc / 4; i += blockDim.x) dst[i] = src[i];
}

__global__ void rmsnorm_pack(const float* __restrict__ in, const float* __restrict__ w,
                             __nv_bfloat16* __restrict__ oh, __nv_bfloat16* __restrict__ ol) {
    long b = (long)blockIdx.x * Dc;
    float s = 0.0f;
    for (int i = threadIdx.x; i < Dc; i += 256) { float v = in[b + i]; s += v * v; }
    s = blockReduceSum(s);
    float inv = rsqrtf(s * (1.0f / Dc) + 1e-6f);
    for (int i = threadIdx.x; i < Dc; i += 256)
        packf2(in[b + i] * inv * w[i], oh[b + i], ol[b + i]);
}

__global__ void rope_pack(const float* __restrict__ qkv,
                          __nv_bfloat16* __restrict__ qh, __nv_bfloat16* __restrict__ ql,
                          __nv_bfloat16* __restrict__ kh, __nv_bfloat16* __restrict__ kl) {
    int idx = blockIdx.x * 256 + threadIdx.x;
    int i = idx & 31;
    int rest = idx >> 5;
    int h = rest & (Hc - 1);
    int rl = rest >> 4;
    int l = rl & (Lc - 1);
    float ts_inv = expf((float)i * -0.28782313662425572f);
    float ang = (float)l * ts_inv;
    float sn, cs;
    sincosf(ang, &sn, &cs);
    long src = (long)rl * 3072 + h * DHc + i;
    long dst = (long)rl * Dc + h * DHc + i;
    float q1 = qkv[src], q2 = qkv[src + 32];
    packf2((q1 * cs - q2 * sn) * 0.125f, qh[dst], ql[dst]);
    packf2((q2 * cs + q1 * sn) * 0.125f, qh[dst + 32], ql[dst + 32]);
    float k1 = qkv[src + 1024], k2 = qkv[src + 1024 + 32];
    packf2(k1 * cs - k2 * sn, kh[dst], kl[dst]);
    packf2(k2 * cs + k1 * sn, kh[dst + 32], kl[dst + 32]);
}

__global__ void vtrans_pack(const float* __restrict__ qkv,
                            __nv_bfloat16* __restrict__ vh, __nv_bfloat16* __restrict__ vl) {
    __shared__ uint32_t t[32][33];
    int bh = blockIdx.z; int b = bh >> 4, h = bh & 15;
    int l0 = blockIdx.x * 32, d0 = blockIdx.y * 32;
    int tx = threadIdx.x, ty = threadIdx.y;
    float val = qkv[(long)(b * Lc + l0 + ty) * 3072 + 2048 + h * DHc + d0 + tx];
    t[ty][tx] = packf(val);
    __syncthreads();
    uint32_t p = t[tx][ty];
    long o = ((long)bh * DHc + d0 + ty) * Lc + l0 + tx;
    vh[o] = __ushort_as_bfloat16((unsigned short)(p & 0xFFFF));
    vl[o] = __ushort_as_bfloat16((unsigned short)(p >> 16));
}

__global__ void softmax_pack(const float* __restrict__ att,
                             __nv_bfloat16* __restrict__ oh, __nv_bfloat16* __restrict__ ol) {
    int qi = blockIdx.x;
    long base = ((long)blockIdx.y * Lc + qi) * Lc;
    int tid = threadIdx.x;
    float vals[4];
    float mx = -FLT_MAX;
    #pragma unroll
    for (int j = 0; j < 4; j++) {
        int kk = tid + j * 256;
        vals[j] = (kk <= qi) ? att[base + kk] : -FLT_MAX;
        mx = fmaxf(mx, vals[j]);
    }
    mx = blockReduceMax(mx);
    float s = 0.0f;
    #pragma unroll
    for (int j = 0; j < 4; j++) {
        int kk = tid + j * 256;
        if (kk <= qi) { vals[j] = __expf(vals[j] - mx); s += vals[j]; }
        else vals[j] = 0.0f;
    }
    s = blockReduceSum(s);
    float inv = 1.0f / s;
    int lim = (qi | 127) + 1;
    #pragma unroll
    for (int j = 0; j < 4; j++) {
        int kk = tid + j * 256;
        if (kk < lim) packf2(vals[j] * inv, oh[base + kk], ol[base + kk]);
    }
}

__global__ void swish_pack(const float* __restrict__ gp,
                           __nv_bfloat16* __restrict__ oh, __nv_bfloat16* __restrict__ ol) {
    int i = blockIdx.x * 256 + threadIdx.x;
    int row = i >> 12, col = i & 4095;
    float gv = gp[(long)row * 8192 + col];
    float pv = gp[(long)row * 8192 + 4096 + col];
    float sw = gv / (1.0f + __expf(-gv)) * pv;
    packf2(sw, oh[i], ol[i]);
}

__global__ void wtrans(const float* __restrict__ W,
                       __nv_bfloat16* __restrict__ Oh, __nv_bfloat16* __restrict__ Ol,
                       int Kd, int Nd, long ostride) {
    __shared__ uint32_t t[32][33];
    long li = (long)blockIdx.z * Kd * Nd;
    long lo_ = (long)blockIdx.z * ostride;
    int n0 = blockIdx.x * 32, k0 = blockIdx.y * 32;
    int tx = threadIdx.x;
    int ty = threadIdx.y;
    float4 v = *(const float4*)(W + li + (long)(k0 + ty) * Nd + n0 + tx * 4);
    t[tx * 4 + 0][ty] = packf(v.x);
    t[tx * 4 + 1][ty] = packf(v.y);
    t[tx * 4 + 2][ty] = packf(v.z);
    t[tx * 4 + 3][ty] = packf(v.w);
    __syncthreads();
    uint32_t p0 = t[ty][tx * 4], p1 = t[ty][tx * 4 + 1], p2 = t[ty][tx * 4 + 2], p3 = t[ty][tx * 4 + 3];
    ushort4 hs = make_ushort4((unsigned short)(p0 & 0xFFFF), (unsigned short)(p1 & 0xFFFF),
                              (unsigned short)(p2 & 0xFFFF), (unsigned short)(p3 & 0xFFFF));
    ushort4 ls = make_ushort4((unsigned short)(p0 >> 16), (unsigned short)(p1 >> 16),
                              (unsigned short)(p2 >> 16), (unsigned short)(p3 >> 16));
    long o = lo_ + (long)(n0 + ty) * Kd + k0 + tx * 4;
    *(ushort4*)(Oh + o) = hs;
    *(ushort4*)(Ol + o) = ls;
}

// ---------------------------------------------------------------------------
// Host
// ---------------------------------------------------------------------------
#define SM128 (2 * (20480 + 128 * 160))   // 81920
#define SM64  (2 * (20480 + 64 * 160))    // 61440

extern "C" void kernel_launch(void* const* d_in, const int* in_sizes, int n_in,
                              void* d_out, int out_size) {
    const int*   tokens = (const int*)d_in[0];
    const float* embed  = (const float*)d_in[1];
    const float* ln1    = (const float*)d_in[2];
    const float* Wq     = (const float*)d_in[3];
    const float* Wk     = (const float*)d_in[4];
    const float* Wv     = (const float*)d_in[5];
    const float* Wo     = (const float*)d_in[6];
    const float* ln2    = (const float*)d_in[7];
    const float* Wg     = (const float*)d_in[8];
    const float* Wp     = (const float*)d_in[9];
    const float* Wd     = (const float*)d_in[10];
    const float* out_ln = (const float*)d_in[11];
    const float* head   = (const float*)d_in[12];

    cudaFuncSetAttribute(gemm_mma<128>, cudaFuncAttributeMaxDynamicSharedMemorySize, SM128);
    cudaFuncSetAttribute(gemm_mma<64>,  cudaFuncAttributeMaxDynamicSharedMemorySize, SM64);

    float *y, *qkv, *att, *gp, *part;
    __nv_bfloat16 *xh, *xl, *qh, *ql, *kh, *kl, *vth, *vtl, *th, *tl, *ph, *pl, *gh, *gl, *wh, *wl;
    cudaGetSymbolAddress((void**)&y,    g_y);
    cudaGetSymbolAddress((void**)&qkv,  g_qkv);
    cudaGetSymbolAddress((void**)&att,  g_att);
    cudaGetSymbolAddress((void**)&gp,   g_gp);
    cudaGetSymbolAddress((void**)&part, g_part);
    cudaGetSymbolAddress((void**)&xh,   g_xh);  cudaGetSymbolAddress((void**)&xl, g_xl);
    cudaGetSymbolAddress((void**)&qh,   g_qh);  cudaGetSymbolAddress((void**)&ql, g_ql);
    cudaGetSymbolAddress((void**)&kh,   g_kh);  cudaGetSymbolAddress((void**)&kl, g_kl);
    cudaGetSymbolAddress((void**)&vth,  g_vth); cudaGetSymbolAddress((void**)&vtl, g_vtl);
    cudaGetSymbolAddress((void**)&th,   g_th);  cudaGetSymbolAddress((void**)&tl, g_tl);
    cudaGetSymbolAddress((void**)&ph,   g_ph);  cudaGetSymbolAddress((void**)&pl, g_pl);
    cudaGetSymbolAddress((void**)&gh,   g_gh);  cudaGetSymbolAddress((void**)&gl, g_gl);
    cudaGetSymbolAddress((void**)&wh,   g_wh);  cudaGetSymbolAddress((void**)&wl, g_wl);

    const long OQKV = 0;
    const long OO   = 25165824;
    const long OGP  = 33554432;
    const long OD   = 100663296;
    const long OH   = 134217728;
    const long MD   = (long)Bc * Lc * Dc;

    dim3 tw(8, 32);
    wtrans<<<dim3(32, 32, 8),   tw>>>(Wq, wh + OQKV,            wl + OQKV,            1024, 1024, 3145728);
    wtrans<<<dim3(32, 32, 8),   tw>>>(Wk, wh + OQKV + 1048576,  wl + OQKV + 1048576,  1024, 1024, 3145728);
    wtrans<<<dim3(32, 32, 8),   tw>>>(Wv, wh + OQKV + 2097152,  wl + OQKV + 2097152,  1024, 1024, 3145728);
    wtrans<<<dim3(32, 32, 8),   tw>>>(Wo, wh + OO,              wl + OO,              1024, 1024, 1048576);
    wtrans<<<dim3(128, 32, 8),  tw>>>(Wg, wh + OGP,             wl + OGP,             1024, 4096, 8388608);
    wtrans<<<dim3(128, 32, 8),  tw>>>(Wp, wh + OGP + 4194304,   wl + OGP + 4194304,   1024, 4096, 8388608);
    wtrans<<<dim3(32, 128, 8),  tw>>>(Wd, wh + OD,              wl + OD,              4096, 1024, 4194304);
    wtrans<<<dim3(1000, 32, 1), tw>>>(head, wh + OH,            wl + OH,              1024, 32000, 0);

    embed_k<<<Bc * Lc, 256>>>(tokens, embed, y);

    const long LL = (long)Lc * Lc;
    const long LD = (long)Lc * Dc;
    dim3 tb(32, 32);

    // initial ln1 norm for layer 0
    rmsnorm_pack<<<Bc * Lc, 256>>>(y, ln1, xh, xl);

    for (int l = 0; l < NL; l++) {
        // merged QKV (x planes already prepared)
        gemm_mma<128><<<dim3(24, 16, 1), 128, SM128>>>(
            xh, xl, wh + OQKV + (long)l * 3145728, wl + OQKV + (long)l * 3145728,
            qkv, 0, 0, 0, 1024, 1024, 1024, 3072, 1, 0, 0, 0, 0, 0, 0, 0);

        rope_pack<<<4096, 256>>>(qkv, qh, ql, kh, kl);
        vtrans_pack<<<dim3(32, 2, 32), tb>>>(qkv, vth, vtl);

        // scores (causal tiles skipped)
        gemm_mma<128><<<dim3(8, 8, 32), 128, SM128>>>(
            qh, ql, kh, kl, att, 0, 0, 0,
            64, 1024, 1024, 1024, Hc,
            LD, 64, LD, 64, (long)Hc * LL, LL, 2);

        softmax_pack<<<dim3(Lc, Bc * Hc), 256>>>(att, ph, pl);

        // AV (K clipped per M-tile), balanced row-block permutation
        gemm_mma<64><<<dim3(1, 8, 32), 128, SM64>>>(
            ph, pl, vth, vtl, 0, th, tl, 0,
            1024, 1024, 1024, 1024, Hc,
            (long)Hc * LL, LL, (long)Hc * DHc * Lc, (long)DHc * Lc, LD, 64, 4 | 8);

        // Wo split-K=2 -> partials; fused reduce + residual + ln2 norm + pack
        gemm_mma<128><<<dim3(8, 16, 2), 128, SM128>>>(
            th, tl, wh + OO + (long)l * 1048576, wl + OO + (long)l * 1048576,
            part, 0, 0, 0, 512, 1024, 1024, 1024, 1,
            512, 0, 512, 0, MD, 0, 0);
        reduce_norm_pack<<<Bc * Lc, 256>>>(y, part, part + MD, ln2 + (long)l * Dc, xh, xl);

        // merged gate+proj
        gemm_mma<128><<<dim3(64, 16, 1), 128, SM128>>>(
            xh, xl, wh + OGP + (long)l * 8388608, wl + OGP + (long)l * 8388608,
            gp, 0, 0, 0, 1024, 1024, 1024, 8192, 1, 0, 0, 0, 0, 0, 0, 0);

        swish_pack<<<32768, 256>>>(gp, gh, gl);

        // Wd split-K=2 -> partials; fused reduce + residual + next-norm + pack
        const float* wnorm = (l + 1 < NL) ? (ln1 + (long)(l + 1) * Dc) : out_ln;
        gemm_mma<128><<<dim3(8, 16, 2), 128, SM128>>>(
            gh, gl, wh + OD + (long)l * 4194304, wl + OD + (long)l * 4194304,
            part, 0, 0, 0, 2048, 4096, 4096, 1024, 1,
            2048, 0, 2048, 0, MD, 0, 0);
        reduce_norm_pack<<<Bc * Lc, 256>>>(y, part, part + MD, wnorm, xh, xl);
    }

    // head GEMM (x planes hold out_ln-normed activations from last fusion)
    gemm_mma<128><<<dim3(250, 16, 1), 128, SM128>>>(
        xh, xl, wh + OH, wl + OH, (float*)d_out, 0, 0, 0,
        1024, 1024, 1024, 32000, 1, 0, 0, 0, 0, 0, 0, 0);
}

// round 15
// speedup vs baseline: 1.0676x; 1.0046x over previous
#include <cuda_runtime.h>
#include <cuda_bf16.h>
#include <mma.h>
#include <math.h>
#include <float.h>
#include <stdint.h>

using namespace nvcuda;

#define Bc 2
#define Lc 1024
#define Dc 1024
#define Hc 16
#define NL 8
#define Vc 32000
#define Fc 4096
#define DHc 64

// ---------------------------------------------------------------------------
// Device-global scratch
// ---------------------------------------------------------------------------
__device__ float g_y[Bc*Lc*Dc];
__device__ float g_qkv[Bc*Lc*3*Dc];
__device__ float g_att[Bc*Hc*Lc*Lc];     // scores; QKV split-K partials alias (used before scores)
__device__ float g_gp[Bc*Lc*2*Fc];
// bf16 hi/lo planes
__device__ __nv_bfloat16 g_xh[Bc*Lc*Dc],  g_xl[Bc*Lc*Dc];
__device__ __nv_bfloat16 g_qh[Bc*Lc*Dc],  g_ql[Bc*Lc*Dc];
__device__ __nv_bfloat16 g_kh[Bc*Lc*Dc],  g_kl[Bc*Lc*Dc];
__device__ __nv_bfloat16 g_vth[Bc*Hc*DHc*Lc], g_vtl[Bc*Hc*DHc*Lc];
__device__ __nv_bfloat16 g_th[Bc*Lc*Dc],  g_tl[Bc*Lc*Dc];
__device__ __nv_bfloat16 g_ph[Bc*Hc*Lc*Lc], g_pl[Bc*Hc*Lc*Lc];
__device__ __nv_bfloat16 g_gh[Bc*Lc*Fc],  g_gl[Bc*Lc*Fc];
__device__ __nv_bfloat16 g_wh[166985728], g_wl[166985728];
// dedicated split-K partial buffers for Wo/Wd (att busy then)
__device__ float g_part[2*Bc*Lc*Dc];

__device__ __forceinline__ uint32_t packf(float v) {
    __nv_bfloat16 h = __float2bfloat16(v);
    float hf = __bfloat162float(h);
    __nv_bfloat16 l = __float2bfloat16(v - hf);
    return (uint32_t)__bfloat16_as_ushort(h) | ((uint32_t)__bfloat16_as_ushort(l) << 16);
}
__device__ __forceinline__ void packf2(float v, __nv_bfloat16& h, __nv_bfloat16& l) {
    h = __float2bfloat16(v);
    l = __float2bfloat16(v - __bfloat162float(h));
}

__device__ __forceinline__ uint32_t smem_u32(const void* p) {
    uint32_t a;
    asm("{ .reg .u64 t; cvta.to.shared.u64 t, %1; cvt.u32.u64 %0, t; }" : "=r"(a) : "l"(p));
    return a;
}
__device__ __forceinline__ void cpasync16(uint32_t dst, const void* src) {
    asm volatile("cp.async.cg.shared.global [%0], [%1], 16;" :: "r"(dst), "l"(src) : "memory");
}
__device__ __forceinline__ void cp_commit() {
    asm volatile("cp.async.commit_group;" ::: "memory");
}
__device__ __forceinline__ void cp_wait1() {
    asm volatile("cp.async.wait_group 1;" ::: "memory");
}

// ---------------------------------------------------------------------------
// Block reductions (blockDim.x == 256)
// ---------------------------------------------------------------------------
__device__ __forceinline__ float blockReduceSum(float v) {
    __shared__ float sh[33];
    int lane = threadIdx.x & 31, wid = threadIdx.x >> 5;
    #pragma unroll
    for (int o = 16; o > 0; o >>= 1) v += __shfl_down_sync(0xffffffffu, v, o);
    if (lane == 0) sh[wid] = v;
    __syncthreads();
    v = (threadIdx.x < 8) ? sh[lane] : 0.0f;
    if (wid == 0) {
        #pragma unroll
        for (int o = 4; o > 0; o >>= 1) v += __shfl_down_sync(0xffffffffu, v, o);
        if (lane == 0) sh[32] = v;
    }
    __syncthreads();
    return sh[32];
}
__device__ __forceinline__ float blockReduceMax(float v) {
    __shared__ float sh[33];
    int lane = threadIdx.x & 31, wid = threadIdx.x >> 5;
    #pragma unroll
    for (int o = 16; o > 0; o >>= 1) v = fmaxf(v, __shfl_down_sync(0xffffffffu, v, o));
    if (lane == 0) sh[wid] = v;
    __syncthreads();
    v = (threadIdx.x < 8) ? sh[lane] : -FLT_MAX;
    if (wid == 0) {
        #pragma unroll
        for (int o = 4; o > 0; o >>= 1) v = fmaxf(v, __shfl_down_sync(0xffffffffu, v, o));
        if (lane == 0) sh[32] = v;
    }
    __syncthreads();
    return sh[32];
}

// ---------------------------------------------------------------------------
// WMMA GEMM (R10 core)
// ---------------------------------------------------------------------------
#define LDS_ 40

template<int BN>
__global__ __launch_bounds__(128, 2) void gemm_mma(
    const __nv_bfloat16* __restrict__ Ahp, const __nv_bfloat16* __restrict__ Alp,
    const __nv_bfloat16* __restrict__ Bhp, const __nv_bfloat16* __restrict__ Blp,
    float* __restrict__ C, __nv_bfloat16* __restrict__ Ch, __nv_bfloat16* __restrict__ Cl,
    const float* __restrict__ R,
    int K, int lda, int ldb, int ldc, int bH,
    long sAb, long sAh, long sBb, long sBh, long sCb, long sCh, int flags)
{
    const int BM = 128;
    const int WN = BN / 2;
    const int NT = WN / 16;
    const int APB = 5120;
    const int BPB = BN * LDS_;
    const int SSZ = (2 * APB + 2 * BPB) * 2;

    int by = blockIdx.y;
    if (flags & 8) by = (by < 4) ? by : 11 - by;
    int row0 = by * BM, col0 = blockIdx.x * BN;
    if ((flags & 2) && col0 >= row0 + BM) return;
    if (flags & 4) { int kc = row0 + BM; if (kc < K) K = kc; }
    int z = blockIdx.z, zb = z / bH, zh = z - zb * bH;
    long aoff = (long)zb * sAb + (long)zh * sAh;
    long boff = (long)zb * sBb + (long)zh * sBh;
    long coff = (long)zb * sCb + (long)zh * sCh;

    extern __shared__ __align__(16) char smraw[];
    uint32_t sbase = smem_u32(smraw);

    int tid = threadIdx.x, wid = tid >> 5, lane = tid & 31;
    int wm = wid & 1, wn = wid >> 1;

    wmma::fragment<wmma::accumulator, 16, 16, 16, float> acc[4][NT];
    if (R) {
        const float* Rb = R + coff;
        #pragma unroll
        for (int i = 0; i < 4; i++)
            #pragma unroll
            for (int j = 0; j < NT; j++)
                wmma::load_matrix_sync(acc[i][j],
                    Rb + (long)(row0 + wm * 64 + i * 16) * ldc + col0 + wn * WN + j * 16,
                    ldc, wmma::mem_row_major);
    } else {
        #pragma unroll
        for (int i = 0; i < 4; i++)
            #pragma unroll
            for (int j = 0; j < NT; j++)
                wmma::fill_fragment(acc[i][j], 0.0f);
    }

    const __nv_bfloat16* Ahg = Ahp + aoff + (long)row0 * lda;
    const __nv_bfloat16* Alg = Alp + aoff + (long)row0 * lda;
    const __nv_bfloat16* Bhg = Bhp + boff + (long)col0 * ldb;
    const __nv_bfloat16* Blg = Blp + boff + (long)col0 * ldb;
    int NC = K >> 5;

    auto issue = [&](int c) {
        uint32_t sb = sbase + (c & 1) * SSZ;
        int kc = c << 5;
        #pragma unroll
        for (int i = 0; i < 4; i++) {
            int lin = tid + i * 128;
            int r = lin >> 2, g = lin & 3;
            long go = (long)r * lda + kc + g * 8;
            uint32_t so = r * 80 + g * 16;
            cpasync16(sb + so, Ahg + go);
            cpasync16(sb + 2 * APB + so, Alg + go);
        }
        #pragma unroll
        for (int i = 0; i < BN / 32; i++) {
            int lin = tid + i * 128;
            int r = lin >> 2, g = lin & 3;
            long go = (long)r * ldb + kc + g * 8;
            uint32_t so = r * 80 + g * 16;
            cpasync16(sb + 4 * APB + so, Bhg + go);
            cpasync16(sb + 4 * APB + 2 * BPB + so, Blg + go);
        }
    };

    issue(0); cp_commit();
    if (NC > 1) issue(1);
    cp_commit();

    for (int c = 0; c < NC; c++) {
        cp_wait1();
        __syncthreads();
        {
            const __nv_bfloat16* base = (const __nv_bfloat16*)(smraw + (c & 1) * SSZ);
            const __nv_bfloat16* Ah = base;
            const __nv_bfloat16* Al = base + APB;
            const __nv_bfloat16* Bh = base + 2 * APB;
            const __nv_bfloat16* Bl = base + 2 * APB + BPB;
            #pragma unroll
            for (int ks = 0; ks < 2; ks++) {
                int k0 = ks * 16;
                wmma::fragment<wmma::matrix_b, 16, 16, 16, __nv_bfloat16, wmma::col_major> fbh[NT], fbl[NT];
                #pragma unroll
                for (int j = 0; j < NT; j++) {
                    wmma::load_matrix_sync(fbh[j], Bh + (wn * WN + j * 16) * LDS_ + k0, LDS_);
                    wmma::load_matrix_sync(fbl[j], Bl + (wn * WN + j * 16) * LDS_ + k0, LDS_);
                }
                #pragma unroll
                for (int i = 0; i < 4; i++) {
                    wmma::fragment<wmma::matrix_a, 16, 16, 16, __nv_bfloat16, wmma::row_major> fah, fal;
                    wmma::load_matrix_sync(fah, Ah + (wm * 64 + i * 16) * LDS_ + k0, LDS_);
                    wmma::load_matrix_sync(fal, Al + (wm * 64 + i * 16) * LDS_ + k0, LDS_);
                    #pragma unroll
                    for (int j = 0; j < NT; j++) {
                        wmma::mma_sync(acc[i][j], fah, fbh[j], acc[i][j]);
                        wmma::mma_sync(acc[i][j], fah, fbl[j], acc[i][j]);
                        wmma::mma_sync(acc[i][j], fal, fbh[j], acc[i][j]);
                    }
                }
            }
        }
        __syncthreads();
        if (c + 2 < NC) issue(c + 2);
        cp_commit();
    }

    if (!Ch) {
        float* Cb = C + coff;
        #pragma unroll
        for (int i = 0; i < 4; i++)
            #pragma unroll
            for (int j = 0; j < NT; j++)
                wmma::store_matrix_sync(
                    Cb + (long)(row0 + wm * 64 + i * 16) * ldc + col0 + wn * WN + j * 16,
                    acc[i][j], ldc, wmma::mem_row_major);
    } else {
        __syncthreads();
        float* wbuf = (float*)smraw + wid * 256;
        #pragma unroll
        for (int i = 0; i < 4; i++)
            #pragma unroll
            for (int j = 0; j < NT; j++) {
                wmma::store_matrix_sync(wbuf, acc[i][j], 16, wmma::mem_row_major);
                __syncwarp();
                int r = lane >> 1, chn = lane & 1;
                const float* src = wbuf + r * 16 + chn * 8;
                __nv_bfloat16 hb[8], lb[8];
                #pragma unroll
                for (int t = 0; t < 8; t++) packf2(src[t], hb[t], lb[t]);
                long off = (long)(row0 + wm * 64 + i * 16 + r) * ldc + col0 + wn * WN + j * 16 + chn * 8 + coff;
                *(uint4*)(Ch + off) = *(uint4*)hb;
                *(uint4*)(Cl + off) = *(uint4*)lb;
                __syncwarp();
            }
    }
}

// ---------------------------------------------------------------------------
// Fused split-K reduce + residual + rmsnorm + pack
// ---------------------------------------------------------------------------
__global__ void reduce_norm_pack(float* __restrict__ y,
                                 const float* __restrict__ p0, const float* __restrict__ p1,
                                 const float* __restrict__ w,
                                 __nv_bfloat16* __restrict__ oh, __nv_bfloat16* __restrict__ ol) {
    long b = (long)blockIdx.x * Dc;
    int tid = threadIdx.x;
    float vals[4];
    float s = 0.0f;
    #pragma unroll
    for (int j = 0; j < 4; j++) {
        int i = tid + j * 256;
        float v = y[b + i] + p0[b + i] + p1[b + i];
        vals[j] = v;
        y[b + i] = v;
        s += v * v;
    }
    s = blockReduceSum(s);
    float inv = rsqrtf(s * (1.0f / Dc) + 1e-6f);
    #pragma unroll
    for (int j = 0; j < 4; j++) {
        int i = tid + j * 256;
        packf2(vals[j] * inv * w[i], oh[b + i], ol[b + i]);
    }
}

// plain split-K sum: out = p0 + p1 (vectorized)
__global__ void reduce2(float* __restrict__ out, const float* __restrict__ p0,
                        const float* __restrict__ p1) {
    int i = blockIdx.x * 256 + threadIdx.x;
    float4 a = ((const float4*)p0)[i];
    float4 b = ((const float4*)p1)[i];
    a.x += b.x; a.y += b.y; a.z += b.z; a.w += b.w;
    ((float4*)out)[i] = a;
}

// ---------------------------------------------------------------------------
// Aux kernels
// ---------------------------------------------------------------------------
__global__ void embed_k(const int* __restrict__ tokens, const float* __restrict__ emb,
                        float* __restrict__ y) {
    int r = blockIdx.x;
    int tok = tokens[r];
    const float4* src = (const float4*)(emb + (long)tok * Dc);
    float4* dst = (float4*)(y + (long)r * Dc);
    for (int i = threadIdx.x; i < Dc / 4; i += blockDim.x) dst[i] = src[i];
}

__global__ void rmsnorm_pack(const float* __restrict__ in, const float* __restrict__ w,
                             __nv_bfloat16* __restrict__ oh, __nv_bfloat16* __restrict__ ol) {
    long b = (long)blockIdx.x * Dc;
    float s = 0.0f;
    for (int i = threadIdx.x; i < Dc; i += 256) { float v = in[b + i]; s += v * v; }
    s = blockReduceSum(s);
    float inv = rsqrtf(s * (1.0f / Dc) + 1e-6f);
    for (int i = threadIdx.x; i < Dc; i += 256)
        packf2(in[b + i] * inv * w[i], oh[b + i], ol[b + i]);
}

__global__ void rope_pack(const float* __restrict__ qkv,
                          __nv_bfloat16* __restrict__ qh, __nv_bfloat16* __restrict__ ql,
                          __nv_bfloat16* __restrict__ kh, __nv_bfloat16* __restrict__ kl) {
    int idx = blockIdx.x * 256 + threadIdx.x;
    int i = idx & 31;
    int rest = idx >> 5;
    int h = rest & (Hc - 1);
    int rl = rest >> 4;
    int l = rl & (Lc - 1);
    float ts_inv = expf((float)i * -0.28782313662425572f);
    float ang = (float)l * ts_inv;
    float sn, cs;
    sincosf(ang, &sn, &cs);
    long src = (long)rl * 3072 + h * DHc + i;
    long dst = (long)rl * Dc + h * DHc + i;
    float q1 = qkv[src], q2 = qkv[src + 32];
    packf2((q1 * cs - q2 * sn) * 0.125f, qh[dst], ql[dst]);
    packf2((q2 * cs + q1 * sn) * 0.125f, qh[dst + 32], ql[dst + 32]);
    float k1 = qkv[src + 1024], k2 = qkv[src + 1024 + 32];
    packf2(k1 * cs - k2 * sn, kh[dst], kl[dst]);
    packf2(k2 * cs + k1 * sn, kh[dst + 32], kl[dst + 32]);
}

__global__ void vtrans_pack(const float* __restrict__ qkv,
                            __nv_bfloat16* __restrict__ vh, __nv_bfloat16* __restrict__ vl) {
    __shared__ uint32_t t[32][33];
    int bh = blockIdx.z; int b = bh >> 4, h = bh & 15;
    int l0 = blockIdx.x * 32, d0 = blockIdx.y * 32;
    int tx = threadIdx.x, ty = threadIdx.y;
    float val = qkv[(long)(b * Lc + l0 + ty) * 3072 + 2048 + h * DHc + d0 + tx];
    t[ty][tx] = packf(val);
    __syncthreads();
    uint32_t p = t[tx][ty];
    long o = ((long)bh * DHc + d0 + ty) * Lc + l0 + tx;
    vh[o] = __ushort_as_bfloat16((unsigned short)(p & 0xFFFF));
    vl[o] = __ushort_as_bfloat16((unsigned short)(p >> 16));
}

__global__ void softmax_pack(const float* __restrict__ att,
                             __nv_bfloat16* __restrict__ oh, __nv_bfloat16* __restrict__ ol) {
    int qi = blockIdx.x;
    long base = ((long)blockIdx.y * Lc + qi) * Lc;
    int tid = threadIdx.x;
    float vals[4];
    float mx = -FLT_MAX;
    #pragma unroll
    for (int j = 0; j < 4; j++) {
        int kk = tid + j * 256;
        vals[j] = (kk <= qi) ? att[base + kk] : -FLT_MAX;
        mx = fmaxf(mx, vals[j]);
    }
    mx = blockReduceMax(mx);
    float s = 0.0f;
    #pragma unroll
    for (int j = 0; j < 4; j++) {
        int kk = tid + j * 256;
        if (kk <= qi) { vals[j] = __expf(vals[j] - mx); s += vals[j]; }
        else vals[j] = 0.0f;
    }
    s = blockReduceSum(s);
    float inv = 1.0f / s;
    int lim = (qi | 127) + 1;
    #pragma unroll
    for (int j = 0; j < 4; j++) {
        int kk = tid + j * 256;
        if (kk < lim) packf2(vals[j] * inv, oh[base + kk], ol[base + kk]);
    }
}

__global__ void swish_pack(const float* __restrict__ gp,
                           __nv_bfloat16* __restrict__ oh, __nv_bfloat16* __restrict__ ol) {
    int i = blockIdx.x * 256 + threadIdx.x;
    int row = i >> 12, col = i & 4095;
    float gv = gp[(long)row * 8192 + col];
    float pv = gp[(long)row * 8192 + 4096 + col];
    float sw = gv / (1.0f + __expf(-gv)) * pv;
    packf2(sw, oh[i], ol[i]);
}

__global__ void wtrans(const float* __restrict__ W,
                       __nv_bfloat16* __restrict__ Oh, __nv_bfloat16* __restrict__ Ol,
                       int Kd, int Nd, long ostride) {
    __shared__ uint32_t t[32][33];
    long li = (long)blockIdx.z * Kd * Nd;
    long lo_ = (long)blockIdx.z * ostride;
    int n0 = blockIdx.x * 32, k0 = blockIdx.y * 32;
    int tx = threadIdx.x;
    int ty = threadIdx.y;
    float4 v = *(const float4*)(W + li + (long)(k0 + ty) * Nd + n0 + tx * 4);
    t[tx * 4 + 0][ty] = packf(v.x);
    t[tx * 4 + 1][ty] = packf(v.y);
    t[tx * 4 + 2][ty] = packf(v.z);
    t[tx * 4 + 3][ty] = packf(v.w);
    __syncthreads();
    uint32_t p0 = t[ty][tx * 4], p1 = t[ty][tx * 4 + 1], p2 = t[ty][tx * 4 + 2], p3 = t[ty][tx * 4 + 3];
    ushort4 hs = make_ushort4((unsigned short)(p0 & 0xFFFF), (unsigned short)(p1 & 0xFFFF),
                              (unsigned short)(p2 & 0xFFFF), (unsigned short)(p3 & 0xFFFF));
    ushort4 ls = make_ushort4((unsigned short)(p0 >> 16), (unsigned short)(p1 >> 16),
                              (unsigned short)(p2 >> 16), (unsigned short)(p3 >> 16));
    long o = lo_ + (long)(n0 + ty) * Kd + k0 + tx * 4;
    *(ushort4*)(Oh + o) = hs;
    *(ushort4*)(Ol + o) = ls;
}

// ---------------------------------------------------------------------------
// Host
// ---------------------------------------------------------------------------
#define SM128 (2 * (20480 + 128 * 160))   // 81920
#define SM64  (2 * (20480 + 64 * 160))    // 61440

extern "C" void kernel_launch(void* const* d_in, const int* in_sizes, int n_in,
                              void* d_out, int out_size) {
    const int*   tokens = (const int*)d_in[0];
    const float* embed  = (const float*)d_in[1];
    const float* ln1    = (const float*)d_in[2];
    const float* Wq     = (const float*)d_in[3];
    const float* Wk     = (const float*)d_in[4];
    const float* Wv     = (const float*)d_in[5];
    const float* Wo     = (const float*)d_in[6];
    const float* ln2    = (const float*)d_in[7];
    const float* Wg     = (const float*)d_in[8];
    const float* Wp     = (const float*)d_in[9];
    const float* Wd     = (const float*)d_in[10];
    const float* out_ln = (const float*)d_in[11];
    const float* head   = (const float*)d_in[12];

    cudaFuncSetAttribute(gemm_mma<128>, cudaFuncAttributeMaxDynamicSharedMemorySize, SM128);
    cudaFuncSetAttribute(gemm_mma<64>,  cudaFuncAttributeMaxDynamicSharedMemorySize, SM64);

    float *y, *qkv, *att, *gp, *part;
    __nv_bfloat16 *xh, *xl, *qh, *ql, *kh, *kl, *vth, *vtl, *th, *tl, *ph, *pl, *gh, *gl, *wh, *wl;
    cudaGetSymbolAddress((void**)&y,    g_y);
    cudaGetSymbolAddress((void**)&qkv,  g_qkv);
    cudaGetSymbolAddress((void**)&att,  g_att);
    cudaGetSymbolAddress((void**)&gp,   g_gp);
    cudaGetSymbolAddress((void**)&part, g_part);
    cudaGetSymbolAddress((void**)&xh,   g_xh);  cudaGetSymbolAddress((void**)&xl, g_xl);
    cudaGetSymbolAddress((void**)&qh,   g_qh);  cudaGetSymbolAddress((void**)&ql, g_ql);
    cudaGetSymbolAddress((void**)&kh,   g_kh);  cudaGetSymbolAddress((void**)&kl, g_kl);
    cudaGetSymbolAddress((void**)&vth,  g_vth); cudaGetSymbolAddress((void**)&vtl, g_vtl);
    cudaGetSymbolAddress((void**)&th,   g_th);  cudaGetSymbolAddress((void**)&tl, g_tl);
    cudaGetSymbolAddress((void**)&ph,   g_ph);  cudaGetSymbolAddress((void**)&pl, g_pl);
    cudaGetSymbolAddress((void**)&gh,   g_gh);  cudaGetSymbolAddress((void**)&gl, g_gl);
    cudaGetSymbolAddress((void**)&wh,   g_wh);  cudaGetSymbolAddress((void**)&wl, g_wl);

    const long OQKV = 0;
    const long OO   = 25165824;
    const long OGP  = 33554432;
    const long OD   = 100663296;
    const long OH   = 134217728;
    const long MD   = (long)Bc * Lc * Dc;       // 2097152
    const long MQ   = (long)Bc * Lc * 3 * Dc;   // 6291456 (QKV partial stride)

    dim3 tw(8, 32);
    wtrans<<<dim3(32, 32, 8),   tw>>>(Wq, wh + OQKV,            wl + OQKV,            1024, 1024, 3145728);
    wtrans<<<dim3(32, 32, 8),   tw>>>(Wk, wh + OQKV + 1048576,  wl + OQKV + 1048576,  1024, 1024, 3145728);
    wtrans<<<dim3(32, 32, 8),   tw>>>(Wv, wh + OQKV + 2097152,  wl + OQKV + 2097152,  1024, 1024, 3145728);
    wtrans<<<dim3(32, 32, 8),   tw>>>(Wo, wh + OO,              wl + OO,              1024, 1024, 1048576);
    wtrans<<<dim3(128, 32, 8),  tw>>>(Wg, wh + OGP,             wl + OGP,             1024, 4096, 8388608);
    wtrans<<<dim3(128, 32, 8),  tw>>>(Wp, wh + OGP + 4194304,   wl + OGP + 4194304,   1024, 4096, 8388608);
    wtrans<<<dim3(32, 128, 8),  tw>>>(Wd, wh + OD,              wl + OD,              4096, 1024, 4194304);
    wtrans<<<dim3(1000, 32, 1), tw>>>(head, wh + OH,            wl + OH,              1024, 32000, 0);

    embed_k<<<Bc * Lc, 256>>>(tokens, embed, y);

    const long LL = (long)Lc * Lc;
    const long LD = (long)Lc * Dc;
    dim3 tb(32, 32);

    // initial ln1 norm for layer 0
    rmsnorm_pack<<<Bc * Lc, 256>>>(y, ln1, xh, xl);

    for (int l = 0; l < NL; l++) {
        // merged QKV with split-K=2 (768 blocks -> 2.6 waves @87% fill);
        // partials alias att (free until scores GEMM)
        gemm_mma<128><<<dim3(24, 16, 2), 128, SM128>>>(
            xh, xl, wh + OQKV + (long)l * 3145728, wl + OQKV + (long)l * 3145728,
            att, 0, 0, 0, 512, 1024, 1024, 3072, 1,
            512, 0, 512, 0, MQ, 0, 0);
        reduce2<<<(int)(MQ / 1024), 256>>>(qkv, att, att + MQ);

        rope_pack<<<4096, 256>>>(qkv, qh, ql, kh, kl);
        vtrans_pack<<<dim3(32, 2, 32), tb>>>(qkv, vth, vtl);

        // scores (causal tiles skipped)
        gemm_mma<128><<<dim3(8, 8, 32), 128, SM128>>>(
            qh, ql, kh, kl, att, 0, 0, 0,
            64, 1024, 1024, 1024, Hc,
            LD, 64, LD, 64, (long)Hc * LL, LL, 2);

        softmax_pack<<<dim3(Lc, Bc * Hc), 256>>>(att, ph, pl);

        // AV (K clipped per M-tile), balanced row-block permutation
        gemm_mma<64><<<dim3(1, 8, 32), 128, SM64>>>(
            ph, pl, vth, vtl, 0, th, tl, 0,
            1024, 1024, 1024, 1024, Hc,
            (long)Hc * LL, LL, (long)Hc * DHc * Lc, (long)DHc * Lc, LD, 64, 4 | 8);

        // Wo split-K=2 -> partials; fused reduce + residual + ln2 norm + pack
        gemm_mma<128><<<dim3(8, 16, 2), 128, SM128>>>(
            th, tl, wh + OO + (long)l * 1048576, wl + OO + (long)l * 1048576,
            part, 0, 0, 0, 512, 1024, 1024, 1024, 1,
            512, 0, 512, 0, MD, 0, 0);
        reduce_norm_pack<<<Bc * Lc, 256>>>(y, part, part + MD, ln2 + (long)l * Dc, xh, xl);

        // merged gate+proj
        gemm_mma<128><<<dim3(64, 16, 1), 128, SM128>>>(
            xh, xl, wh + OGP + (long)l * 8388608, wl + OGP + (long)l * 8388608,
            gp, 0, 0, 0, 1024, 1024, 1024, 8192, 1, 0, 0, 0, 0, 0, 0, 0);

        swish_pack<<<32768, 256>>>(gp, gh, gl);

        // Wd split-K=2 -> partials; fused reduce + residual + next-norm + pack
        const float* wnorm = (l + 1 < NL) ? (ln1 + (long)(l + 1) * Dc) : out_ln;
        gemm_mma<128><<<dim3(8, 16, 2), 128, SM128>>>(
            gh, gl, wh + OD + (long)l * 4194304, wl + OD + (long)l * 4194304,
            part, 0, 0, 0, 2048, 4096, 4096, 1024, 1,
            2048, 0, 2048, 0, MD, 0, 0);
        reduce_norm_pack<<<Bc * Lc, 256>>>(y, part, part + MD, wnorm, xh, xl);
    }

    // head GEMM (x planes hold out_ln-normed activations from last fusion)
    gemm_mma<128><<<dim3(250, 16, 1), 128, SM128>>>(
        xh, xl, wh + OH, wl + OH, (float*)d_out, 0, 0, 0,
        1024, 1024, 1024, 32000, 1, 0, 0, 0, 0, 0, 0, 0);
}

// round 16
// speedup vs baseline: 1.0864x; 1.0175x over previous
#include <cuda_runtime.h>
#include <cuda_bf16.h>
#include <mma.h>
#include <math.h>
#include <float.h>
#include <stdint.h>

using namespace nvcuda;

#define Bc 2
#define Lc 1024
#define Dc 1024
#define Hc 16
#define NL 8
#define Vc 32000
#define Fc 4096
#define DHc 64

// ---------------------------------------------------------------------------
// Device-global scratch
// ---------------------------------------------------------------------------
__device__ float g_y[Bc*Lc*Dc];
__device__ float g_qkv[Bc*Lc*3*Dc];
__device__ float g_att[Bc*Hc*Lc*Lc];     // scores; QKV split-K partials alias
// bf16 hi/lo planes
__device__ __nv_bfloat16 g_xh[Bc*Lc*Dc],  g_xl[Bc*Lc*Dc];
__device__ __nv_bfloat16 g_qh[Bc*Lc*Dc],  g_ql[Bc*Lc*Dc];
__device__ __nv_bfloat16 g_kh[Bc*Lc*Dc],  g_kl[Bc*Lc*Dc];
__device__ __nv_bfloat16 g_vth[Bc*Hc*DHc*Lc], g_vtl[Bc*Hc*DHc*Lc];
__device__ __nv_bfloat16 g_th[Bc*Lc*Dc],  g_tl[Bc*Lc*Dc];
__device__ __nv_bfloat16 g_ph[Bc*Hc*Lc*Lc], g_pl[Bc*Hc*Lc*Lc];
__device__ __nv_bfloat16 g_gh[Bc*Lc*Fc],  g_gl[Bc*Lc*Fc];
__device__ __nv_bfloat16 g_wh[166985728], g_wl[166985728];
// dedicated split-K partial buffers for Wo/Wd
__device__ float g_part[2*Bc*Lc*Dc];

__device__ __forceinline__ uint32_t packf(float v) {
    __nv_bfloat16 h = __float2bfloat16(v);
    float hf = __bfloat162float(h);
    __nv_bfloat16 l = __float2bfloat16(v - hf);
    return (uint32_t)__bfloat16_as_ushort(h) | ((uint32_t)__bfloat16_as_ushort(l) << 16);
}
__device__ __forceinline__ void packf2(float v, __nv_bfloat16& h, __nv_bfloat16& l) {
    h = __float2bfloat16(v);
    l = __float2bfloat16(v - __bfloat162float(h));
}

__device__ __forceinline__ uint32_t smem_u32(const void* p) {
    uint32_t a;
    asm("{ .reg .u64 t; cvta.to.shared.u64 t, %1; cvt.u32.u64 %0, t; }" : "=r"(a) : "l"(p));
    return a;
}
__device__ __forceinline__ void cpasync16(uint32_t dst, const void* src) {
    asm volatile("cp.async.cg.shared.global [%0], [%1], 16;" :: "r"(dst), "l"(src) : "memory");
}
__device__ __forceinline__ void cp_commit() {
    asm volatile("cp.async.commit_group;" ::: "memory");
}
__device__ __forceinline__ void cp_wait1() {
    asm volatile("cp.async.wait_group 1;" ::: "memory");
}

// ---------------------------------------------------------------------------
// Block reductions (blockDim.x == 256)
// ---------------------------------------------------------------------------
__device__ __forceinline__ float blockReduceSum(float v) {
    __shared__ float sh[33];
    int lane = threadIdx.x & 31, wid = threadIdx.x >> 5;
    #pragma unroll
    for (int o = 16; o > 0; o >>= 1) v += __shfl_down_sync(0xffffffffu, v, o);
    if (lane == 0) sh[wid] = v;
    __syncthreads();
    v = (threadIdx.x < 8) ? sh[lane] : 0.0f;
    if (wid == 0) {
        #pragma unroll
        for (int o = 4; o > 0; o >>= 1) v += __shfl_down_sync(0xffffffffu, v, o);
        if (lane == 0) sh[32] = v;
    }
    __syncthreads();
    return sh[32];
}
__device__ __forceinline__ float blockReduceMax(float v) {
    __shared__ float sh[33];
    int lane = threadIdx.x & 31, wid = threadIdx.x >> 5;
    #pragma unroll
    for (int o = 16; o > 0; o >>= 1) v = fmaxf(v, __shfl_down_sync(0xffffffffu, v, o));
    if (lane == 0) sh[wid] = v;
    __syncthreads();
    v = (threadIdx.x < 8) ? sh[lane] : -FLT_MAX;
    if (wid == 0) {
        #pragma unroll
        for (int o = 4; o > 0; o >>= 1) v = fmaxf(v, __shfl_down_sync(0xffffffffu, v, o));
        if (lane == 0) sh[32] = v;
    }
    __syncthreads();
    return sh[32];
}

// ---------------------------------------------------------------------------
// WMMA GEMM (R10 core) + flag16 swish-fused epilogue.
// flags: bit1 causal skip, bit2 K clip, bit3 AV row perm,
//        bit4(16) swish epilogue: tile cols = 64 gate + 64 proj interleaved;
//                 writes 64 packed outputs/row to Ch/Cl with col base bx*64.
// ---------------------------------------------------------------------------
#define LDS_ 40

template<int BN>
__global__ __launch_bounds__(128, 2) void gemm_mma(
    const __nv_bfloat16* __restrict__ Ahp, const __nv_bfloat16* __restrict__ Alp,
    const __nv_bfloat16* __restrict__ Bhp, const __nv_bfloat16* __restrict__ Blp,
    float* __restrict__ C, __nv_bfloat16* __restrict__ Ch, __nv_bfloat16* __restrict__ Cl,
    const float* __restrict__ R,
    int K, int lda, int ldb, int ldc, int bH,
    long sAb, long sAh, long sBb, long sBh, long sCb, long sCh, int flags)
{
    const int BM = 128;
    const int WN = BN / 2;
    const int NT = WN / 16;
    const int APB = 5120;
    const int BPB = BN * LDS_;
    const int SSZ = (2 * APB + 2 * BPB) * 2;

    int by = blockIdx.y;
    if (flags & 8) by = (by < 4) ? by : 11 - by;
    int row0 = by * BM, col0 = blockIdx.x * BN;
    if ((flags & 2) && col0 >= row0 + BM) return;
    if (flags & 4) { int kc = row0 + BM; if (kc < K) K = kc; }
    int z = blockIdx.z, zb = z / bH, zh = z - zb * bH;
    long aoff = (long)zb * sAb + (long)zh * sAh;
    long boff = (long)zb * sBb + (long)zh * sBh;
    long coff = (long)zb * sCb + (long)zh * sCh;

    extern __shared__ __align__(16) char smraw[];
    uint32_t sbase = smem_u32(smraw);

    int tid = threadIdx.x, wid = tid >> 5, lane = tid & 31;
    int wm = wid & 1, wn = wid >> 1;

    wmma::fragment<wmma::accumulator, 16, 16, 16, float> acc[4][NT];
    if (R) {
        const float* Rb = R + coff;
        #pragma unroll
        for (int i = 0; i < 4; i++)
            #pragma unroll
            for (int j = 0; j < NT; j++)
                wmma::load_matrix_sync(acc[i][j],
                    Rb + (long)(row0 + wm * 64 + i * 16) * ldc + col0 + wn * WN + j * 16,
                    ldc, wmma::mem_row_major);
    } else {
        #pragma unroll
        for (int i = 0; i < 4; i++)
            #pragma unroll
            for (int j = 0; j < NT; j++)
                wmma::fill_fragment(acc[i][j], 0.0f);
    }

    const __nv_bfloat16* Ahg = Ahp + aoff + (long)row0 * lda;
    const __nv_bfloat16* Alg = Alp + aoff + (long)row0 * lda;
    const __nv_bfloat16* Bhg = Bhp + boff + (long)col0 * ldb;
    const __nv_bfloat16* Blg = Blp + boff + (long)col0 * ldb;
    int NC = K >> 5;

    auto issue = [&](int c) {
        uint32_t sb = sbase + (c & 1) * SSZ;
        int kc = c << 5;
        #pragma unroll
        for (int i = 0; i < 4; i++) {
            int lin = tid + i * 128;
            int r = lin >> 2, g = lin & 3;
            long go = (long)r * lda + kc + g * 8;
            uint32_t so = r * 80 + g * 16;
            cpasync16(sb + so, Ahg + go);
            cpasync16(sb + 2 * APB + so, Alg + go);
        }
        #pragma unroll
        for (int i = 0; i < BN / 32; i++) {
            int lin = tid + i * 128;
            int r = lin >> 2, g = lin & 3;
            long go = (long)r * ldb + kc + g * 8;
            uint32_t so = r * 80 + g * 16;
            cpasync16(sb + 4 * APB + so, Bhg + go);
            cpasync16(sb + 4 * APB + 2 * BPB + so, Blg + go);
        }
    };

    issue(0); cp_commit();
    if (NC > 1) issue(1);
    cp_commit();

    for (int c = 0; c < NC; c++) {
        cp_wait1();
        __syncthreads();
        {
            const __nv_bfloat16* base = (const __nv_bfloat16*)(smraw + (c & 1) * SSZ);
            const __nv_bfloat16* Ah = base;
            const __nv_bfloat16* Al = base + APB;
            const __nv_bfloat16* Bh = base + 2 * APB;
            const __nv_bfloat16* Bl = base + 2 * APB + BPB;
            #pragma unroll
            for (int ks = 0; ks < 2; ks++) {
                int k0 = ks * 16;
                wmma::fragment<wmma::matrix_b, 16, 16, 16, __nv_bfloat16, wmma::col_major> fbh[NT], fbl[NT];
                #pragma unroll
                for (int j = 0; j < NT; j++) {
                    wmma::load_matrix_sync(fbh[j], Bh + (wn * WN + j * 16) * LDS_ + k0, LDS_);
                    wmma::load_matrix_sync(fbl[j], Bl + (wn * WN + j * 16) * LDS_ + k0, LDS_);
                }
                #pragma unroll
                for (int i = 0; i < 4; i++) {
                    wmma::fragment<wmma::matrix_a, 16, 16, 16, __nv_bfloat16, wmma::row_major> fah, fal;
                    wmma::load_matrix_sync(fah, Ah + (wm * 64 + i * 16) * LDS_ + k0, LDS_);
                    wmma::load_matrix_sync(fal, Al + (wm * 64 + i * 16) * LDS_ + k0, LDS_);
                    #pragma unroll
                    for (int j = 0; j < NT; j++) {
                        wmma::mma_sync(acc[i][j], fah, fbh[j], acc[i][j]);
                        wmma::mma_sync(acc[i][j], fah, fbl[j], acc[i][j]);
                        wmma::mma_sync(acc[i][j], fal, fbh[j], acc[i][j]);
                    }
                }
            }
        }
        __syncthreads();
        if (c + 2 < NC) issue(c + 2);
        cp_commit();
    }

    if (flags & 16) {
        // swish-fused epilogue: stage full 128x128 fp32 tile, combine gate/proj halves
        __syncthreads();
        float* st = (float*)smraw;           // pitch 132 floats; 67584 B <= 81920
        #pragma unroll
        for (int i = 0; i < 4; i++)
            #pragma unroll
            for (int j = 0; j < NT; j++)
                wmma::store_matrix_sync(st + (wm * 64 + i * 16) * 132 + wn * WN + j * 16,
                                        acc[i][j], 132, wmma::mem_row_major);
        __syncthreads();
        int r = tid;                          // 128 threads = 128 rows
        long ob = (long)(row0 + r) * ldc + blockIdx.x * 64;
        const float* rowp = st + r * 132;
        #pragma unroll
        for (int c8 = 0; c8 < 64; c8 += 8) {
            unsigned short hb[8], lb[8];
            #pragma unroll
            for (int t = 0; t < 8; t++) {
                float gv = rowp[c8 + t];
                float pv = rowp[64 + c8 + t];
                float sw = gv / (1.0f + __expf(-gv)) * pv;
                __nv_bfloat16 hh, ll;
                packf2(sw, hh, ll);
                hb[t] = __bfloat16_as_ushort(hh);
                lb[t] = __bfloat16_as_ushort(ll);
            }
            *(uint4*)(Ch + ob + c8) = *(uint4*)hb;
            *(uint4*)(Cl + ob + c8) = *(uint4*)lb;
        }
    } else if (!Ch) {
        float* Cb = C + coff;
        #pragma unroll
        for (int i = 0; i < 4; i++)
            #pragma unroll
            for (int j = 0; j < NT; j++)
                wmma::store_matrix_sync(
                    Cb + (long)(row0 + wm * 64 + i * 16) * ldc + col0 + wn * WN + j * 16,
                    acc[i][j], ldc, wmma::mem_row_major);
    } else {
        __syncthreads();
        float* wbuf = (float*)smraw + wid * 256;
        #pragma unroll
        for (int i = 0; i < 4; i++)
            #pragma unroll
            for (int j = 0; j < NT; j++) {
                wmma::store_matrix_sync(wbuf, acc[i][j], 16, wmma::mem_row_major);
                __syncwarp();
                int r = lane >> 1, chn = lane & 1;
                const float* src = wbuf + r * 16 + chn * 8;
                __nv_bfloat16 hb[8], lb[8];
                #pragma unroll
                for (int t = 0; t < 8; t++) packf2(src[t], hb[t], lb[t]);
                long off = (long)(row0 + wm * 64 + i * 16 + r) * ldc + col0 + wn * WN + j * 16 + chn * 8 + coff;
                *(uint4*)(Ch + off) = *(uint4*)hb;
                *(uint4*)(Cl + off) = *(uint4*)lb;
                __syncwarp();
            }
    }
}

// ---------------------------------------------------------------------------
// Fused split-K reduce + residual + rmsnorm + pack
// ---------------------------------------------------------------------------
__global__ void reduce_norm_pack(float* __restrict__ y,
                                 const float* __restrict__ p0, const float* __restrict__ p1,
                                 const float* __restrict__ w,
                                 __nv_bfloat16* __restrict__ oh, __nv_bfloat16* __restrict__ ol) {
    long b = (long)blockIdx.x * Dc;
    int tid = threadIdx.x;
    float vals[4];
    float s = 0.0f;
    #pragma unroll
    for (int j = 0; j < 4; j++) {
        int i = tid + j * 256;
        float v = y[b + i] + p0[b + i] + p1[b + i];
        vals[j] = v;
        y[b + i] = v;
        s += v * v;
    }
    s = blockReduceSum(s);
    float inv = rsqrtf(s * (1.0f / Dc) + 1e-6f);
    #pragma unroll
    for (int j = 0; j < 4; j++) {
        int i = tid + j * 256;
        packf2(vals[j] * inv * w[i], oh[b + i], ol[b + i]);
    }
}

// plain split-K sum: out = p0 + p1
__global__ void reduce2(float* __restrict__ out, const float* __restrict__ p0,
                        const float* __restrict__ p1) {
    int i = blockIdx.x * 256 + threadIdx.x;
    float4 a = ((const float4*)p0)[i];
    float4 b = ((const float4*)p1)[i];
    a.x += b.x; a.y += b.y; a.z += b.z; a.w += b.w;
    ((float4*)out)[i] = a;
}

// ---------------------------------------------------------------------------
// Aux kernels
// ---------------------------------------------------------------------------
__global__ void embed_k(const int* __restrict__ tokens, const float* __restrict__ emb,
                        float* __restrict__ y) {
    int r = blockIdx.x;
    int tok = tokens[r];
    const float4* src = (const float4*)(emb + (long)tok * Dc);
    float4* dst = (float4*)(y + (long)r * Dc);
    for (int i = threadIdx.x; i < Dc / 4; i += blockDim.x) dst[i] = src[i];
}

__global__ void rmsnorm_pack(const float* __restrict__ in, const float* __restrict__ w,
                             __nv_bfloat16* __restrict__ oh, __nv_bfloat16* __restrict__ ol) {
    long b = (long)blockIdx.x * Dc;
    float s = 0.0f;
    for (int i = threadIdx.x; i < Dc; i += 256) { float v = in[b + i]; s += v * v; }
    s = blockReduceSum(s);
    float inv = rsqrtf(s * (1.0f / Dc) + 1e-6f);
    for (int i = threadIdx.x; i < Dc; i += 256)
        packf2(in[b + i] * inv * w[i], oh[b + i], ol[b + i]);
}

__global__ void rope_pack(const float* __restrict__ qkv,
                          __nv_bfloat16* __restrict__ qh, __nv_bfloat16* __restrict__ ql,
                          __nv_bfloat16* __restrict__ kh, __nv_bfloat16* __restrict__ kl) {
    int idx = blockIdx.x * 256 + threadIdx.x;
    int i = idx & 31;
    int rest = idx >> 5;
    int h = rest & (Hc - 1);
    int rl = rest >> 4;
    int l = rl & (Lc - 1);
    float ts_inv = expf((float)i * -0.28782313662425572f);
    float ang = (float)l * ts_inv;
    float sn, cs;
    sincosf(ang, &sn, &cs);
    long src = (long)rl * 3072 + h * DHc + i;
    long dst = (long)rl * Dc + h * DHc + i;
    float q1 = qkv[src], q2 = qkv[src + 32];
    packf2((q1 * cs - q2 * sn) * 0.125f, qh[dst], ql[dst]);
    packf2((q2 * cs + q1 * sn) * 0.125f, qh[dst + 32], ql[dst + 32]);
    float k1 = qkv[src + 1024], k2 = qkv[src + 1024 + 32];
    packf2(k1 * cs - k2 * sn, kh[dst], kl[dst]);
    packf2(k2 * cs + k1 * sn, kh[dst + 32], kl[dst + 32]);
}

__global__ void vtrans_pack(const float* __restrict__ qkv,
                            __nv_bfloat16* __restrict__ vh, __nv_bfloat16* __restrict__ vl) {
    __shared__ uint32_t t[32][33];
    int bh = blockIdx.z; int b = bh >> 4, h = bh & 15;
    int l0 = blockIdx.x * 32, d0 = blockIdx.y * 32;
    int tx = threadIdx.x, ty = threadIdx.y;
    float val = qkv[(long)(b * Lc + l0 + ty) * 3072 + 2048 + h * DHc + d0 + tx];
    t[ty][tx] = packf(val);
    __syncthreads();
    uint32_t p = t[tx][ty];
    long o = ((long)bh * DHc + d0 + ty) * Lc + l0 + tx;
    vh[o] = __ushort_as_bfloat16((unsigned short)(p & 0xFFFF));
    vl[o] = __ushort_as_bfloat16((unsigned short)(p >> 16));
}

__global__ void softmax_pack(const float* __restrict__ att,
                             __nv_bfloat16* __restrict__ oh, __nv_bfloat16* __restrict__ ol) {
    int qi = blockIdx.x;
    long base = ((long)blockIdx.y * Lc + qi) * Lc;
    int tid = threadIdx.x;
    float vals[4];
    float mx = -FLT_MAX;
    #pragma unroll
    for (int j = 0; j < 4; j++) {
        int kk = tid + j * 256;
        vals[j] = (kk <= qi) ? att[base + kk] : -FLT_MAX;
        mx = fmaxf(mx, vals[j]);
    }
    mx = blockReduceMax(mx);
    float s = 0.0f;
    #pragma unroll
    for (int j = 0; j < 4; j++) {
        int kk = tid + j * 256;
        if (kk <= qi) { vals[j] = __expf(vals[j] - mx); s += vals[j]; }
        else vals[j] = 0.0f;
    }
    s = blockReduceSum(s);
    float inv = 1.0f / s;
    int lim = (qi | 127) + 1;
    #pragma unroll
    for (int j = 0; j < 4; j++) {
        int kk = tid + j * 256;
        if (kk < lim) packf2(vals[j] * inv, oh[base + kk], ol[base + kk]);
    }
}

// Transpose + split-pack; ilv: 0 = plain, 1 = gate interleave, 2 = proj interleave
__global__ void wtrans(const float* __restrict__ W,
                       __nv_bfloat16* __restrict__ Oh, __nv_bfloat16* __restrict__ Ol,
                       int Kd, int Nd, long ostride, int ilv) {
    __shared__ uint32_t t[32][33];
    long li = (long)blockIdx.z * Kd * Nd;
    long lo_ = (long)blockIdx.z * ostride;
    int n0 = blockIdx.x * 32, k0 = blockIdx.y * 32;
    int tx = threadIdx.x;
    int ty = threadIdx.y;
    float4 v = *(const float4*)(W + li + (long)(k0 + ty) * Nd + n0 + tx * 4);
    t[tx * 4 + 0][ty] = packf(v.x);
    t[tx * 4 + 1][ty] = packf(v.y);
    t[tx * 4 + 2][ty] = packf(v.z);
    t[tx * 4 + 3][ty] = packf(v.w);
    __syncthreads();
    uint32_t p0 = t[ty][tx * 4], p1 = t[ty][tx * 4 + 1], p2 = t[ty][tx * 4 + 2], p3 = t[ty][tx * 4 + 3];
    ushort4 hs = make_ushort4((unsigned short)(p0 & 0xFFFF), (unsigned short)(p1 & 0xFFFF),
                              (unsigned short)(p2 & 0xFFFF), (unsigned short)(p3 & 0xFFFF));
    ushort4 ls = make_ushort4((unsigned short)(p0 >> 16), (unsigned short)(p1 >> 16),
                              (unsigned short)(p2 >> 16), (unsigned short)(p3 >> 16));
    int n = n0 + ty;
    int orow = n;
    if (ilv) orow = (n >> 6) * 128 + (n & 63) + ((ilv == 2) ? 64 : 0);
    long o = lo_ + (long)orow * Kd + k0 + tx * 4;
    *(ushort4*)(Oh + o) = hs;
    *(ushort4*)(Ol + o) = ls;
}

// ---------------------------------------------------------------------------
// Host
// ---------------------------------------------------------------------------
#define SM128 (2 * (20480 + 128 * 160))   // 81920
#define SM64  (2 * (20480 + 64 * 160))    // 61440

extern "C" void kernel_launch(void* const* d_in, const int* in_sizes, int n_in,
                              void* d_out, int out_size) {
    const int*   tokens = (const int*)d_in[0];
    const float* embed  = (const float*)d_in[1];
    const float* ln1    = (const float*)d_in[2];
    const float* Wq     = (const float*)d_in[3];
    const float* Wk     = (const float*)d_in[4];
    const float* Wv     = (const float*)d_in[5];
    const float* Wo     = (const float*)d_in[6];
    const float* ln2    = (const float*)d_in[7];
    const float* Wg     = (const float*)d_in[8];
    const float* Wp     = (const float*)d_in[9];
    const float* Wd     = (const float*)d_in[10];
    const float* out_ln = (const float*)d_in[11];
    const float* head   = (const float*)d_in[12];

    cudaFuncSetAttribute(gemm_mma<128>, cudaFuncAttributeMaxDynamicSharedMemorySize, SM128);
    cudaFuncSetAttribute(gemm_mma<64>,  cudaFuncAttributeMaxDynamicSharedMemorySize, SM64);

    float *y, *qkv, *att, *part;
    __nv_bfloat16 *xh, *xl, *qh, *ql, *kh, *kl, *vth, *vtl, *th, *tl, *ph, *pl, *gh, *gl, *wh, *wl;
    cudaGetSymbolAddress((void**)&y,    g_y);
    cudaGetSymbolAddress((void**)&qkv,  g_qkv);
    cudaGetSymbolAddress((void**)&att,  g_att);
    cudaGetSymbolAddress((void**)&part, g_part);
    cudaGetSymbolAddress((void**)&xh,   g_xh);  cudaGetSymbolAddress((void**)&xl, g_xl);
    cudaGetSymbolAddress((void**)&qh,   g_qh);  cudaGetSymbolAddress((void**)&ql, g_ql);
    cudaGetSymbolAddress((void**)&kh,   g_kh);  cudaGetSymbolAddress((void**)&kl, g_kl);
    cudaGetSymbolAddress((void**)&vth,  g_vth); cudaGetSymbolAddress((void**)&vtl, g_vtl);
    cudaGetSymbolAddress((void**)&th,   g_th);  cudaGetSymbolAddress((void**)&tl, g_tl);
    cudaGetSymbolAddress((void**)&ph,   g_ph);  cudaGetSymbolAddress((void**)&pl, g_pl);
    cudaGetSymbolAddress((void**)&gh,   g_gh);  cudaGetSymbolAddress((void**)&gl, g_gl);
    cudaGetSymbolAddress((void**)&wh,   g_wh);  cudaGetSymbolAddress((void**)&wl, g_wl);

    const long OQKV = 0;
    const long OO   = 25165824;
    const long OGP  = 33554432;     // 8 x [8192 x 1024] interleaved gate/proj
    const long OD   = 100663296;
    const long OH   = 134217728;
    const long MD   = (long)Bc * Lc * Dc;       // 2097152
    const long MQ   = (long)Bc * Lc * 3 * Dc;   // 6291456

    dim3 tw(8, 32);
    wtrans<<<dim3(32, 32, 8),   tw>>>(Wq, wh + OQKV,            wl + OQKV,            1024, 1024, 3145728, 0);
    wtrans<<<dim3(32, 32, 8),   tw>>>(Wk, wh + OQKV + 1048576,  wl + OQKV + 1048576,  1024, 1024, 3145728, 0);
    wtrans<<<dim3(32, 32, 8),   tw>>>(Wv, wh + OQKV + 2097152,  wl + OQKV + 2097152,  1024, 1024, 3145728, 0);
    wtrans<<<dim3(32, 32, 8),   tw>>>(Wo, wh + OO,              wl + OO,              1024, 1024, 1048576, 0);
    wtrans<<<dim3(128, 32, 8),  tw>>>(Wg, wh + OGP,             wl + OGP,             1024, 4096, 8388608, 1);
    wtrans<<<dim3(128, 32, 8),  tw>>>(Wp, wh + OGP,             wl + OGP,             1024, 4096, 8388608, 2);
    wtrans<<<dim3(32, 128, 8),  tw>>>(Wd, wh + OD,              wl + OD,              4096, 1024, 4194304, 0);
    wtrans<<<dim3(1000, 32, 1), tw>>>(head, wh + OH,            wl + OH,              1024, 32000, 0, 0);

    embed_k<<<Bc * Lc, 256>>>(tokens, embed, y);

    const long LL = (long)Lc * Lc;
    const long LD = (long)Lc * Dc;
    dim3 tb(32, 32);

    // initial ln1 norm for layer 0
    rmsnorm_pack<<<Bc * Lc, 256>>>(y, ln1, xh, xl);

    for (int l = 0; l < NL; l++) {
        // merged QKV with split-K=2 (partials alias att)
        gemm_mma<128><<<dim3(24, 16, 2), 128, SM128>>>(
            xh, xl, wh + OQKV + (long)l * 3145728, wl + OQKV + (long)l * 3145728,
            att, 0, 0, 0, 512, 1024, 1024, 3072, 1,
            512, 0, 512, 0, MQ, 0, 0);
        reduce2<<<(int)(MQ / 1024), 256>>>(qkv, att, att + MQ);

        rope_pack<<<4096, 256>>>(qkv, qh, ql, kh, kl);
        vtrans_pack<<<dim3(32, 2, 32), tb>>>(qkv, vth, vtl);

        // scores (causal tiles skipped)
        gemm_mma<128><<<dim3(8, 8, 32), 128, SM128>>>(
            qh, ql, kh, kl, att, 0, 0, 0,
            64, 1024, 1024, 1024, Hc,
            LD, 64, LD, 64, (long)Hc * LL, LL, 2);

        softmax_pack<<<dim3(Lc, Bc * Hc), 256>>>(att, ph, pl);

        // AV (K clipped per M-tile), balanced row-block permutation
        gemm_mma<64><<<dim3(1, 8, 32), 128, SM64>>>(
            ph, pl, vth, vtl, 0, th, tl, 0,
            1024, 1024, 1024, 1024, Hc,
            (long)Hc * LL, LL, (long)Hc * DHc * Lc, (long)DHc * Lc, LD, 64, 4 | 8);

        // Wo split-K=2 -> partials; fused reduce + residual + ln2 norm + pack
        gemm_mma<128><<<dim3(8, 16, 2), 128, SM128>>>(
            th, tl, wh + OO + (long)l * 1048576, wl + OO + (long)l * 1048576,
            part, 0, 0, 0, 512, 1024, 1024, 1024, 1,
            512, 0, 512, 0, MD, 0, 0);
        reduce_norm_pack<<<Bc * Lc, 256>>>(y, part, part + MD, ln2 + (long)l * Dc, xh, xl);

        // merged gate+proj with fused swish epilogue (interleaved weights);
        // output ldc = Fc, col base = bx*64 inside kernel
        gemm_mma<128><<<dim3(64, 16, 1), 128, SM128>>>(
            xh, xl, wh + OGP + (long)l * 8388608, wl + OGP + (long)l * 8388608,
            0, gh, gl, 0, 1024, 1024, 1024, Fc, 1, 0, 0, 0, 0, 0, 0, 16);

        // Wd split-K=2 -> partials; fused reduce + residual + next-norm + pack
        const float* wnorm = (l + 1 < NL) ? (ln1 + (long)(l + 1) * Dc) : out_ln;
        gemm_mma<128><<<dim3(8, 16, 2), 128, SM128>>>(
            gh, gl, wh + OD + (long)l * 4194304, wl + OD + (long)l * 4194304,
            part, 0, 0, 0, 2048, 4096, 4096, 1024, 1,
            2048, 0, 2048, 0, MD, 0, 0);
        reduce_norm_pack<<<Bc * Lc, 256>>>(y, part, part + MD, wnorm, xh, xl);
    }

    // head GEMM (x planes hold out_ln-normed activations)
    gemm_mma<128><<<dim3(250, 16, 1), 128, SM128>>>(
        xh, xl, wh + OH, wl + OH, (float*)d_out, 0, 0, 0,
        1024, 1024, 1024, 32000, 1, 0, 0, 0, 0, 0, 0, 0);
}

// round 17
// speedup vs baseline: 1.0884x; 1.0018x over previous
#include <cuda_runtime.h>
#include <cuda_bf16.h>
#include <mma.h>
#include <math.h>
#include <float.h>
#include <stdint.h>

using namespace nvcuda;

#define Bc 2
#define Lc 1024
#define Dc 1024
#define Hc 16
#define NL 8
#define Vc 32000
#define Fc 4096
#define DHc 64

// ---------------------------------------------------------------------------
// Device-global scratch
// ---------------------------------------------------------------------------
__device__ float g_y[Bc*Lc*Dc];
__device__ float g_att[Bc*Hc*Lc*Lc];     // scores; QKV split-K partials alias
// bf16 hi/lo planes
__device__ __nv_bfloat16 g_xh[Bc*Lc*Dc],  g_xl[Bc*Lc*Dc];
__device__ __nv_bfloat16 g_qh[Bc*Lc*Dc],  g_ql[Bc*Lc*Dc];
__device__ __nv_bfloat16 g_kh[Bc*Lc*Dc],  g_kl[Bc*Lc*Dc];
__device__ __nv_bfloat16 g_vth[Bc*Hc*DHc*Lc], g_vtl[Bc*Hc*DHc*Lc];
__device__ __nv_bfloat16 g_th[Bc*Lc*Dc],  g_tl[Bc*Lc*Dc];
__device__ __nv_bfloat16 g_ph[Bc*Hc*Lc*Lc], g_pl[Bc*Hc*Lc*Lc];
__device__ __nv_bfloat16 g_gh[Bc*Lc*Fc],  g_gl[Bc*Lc*Fc];
__device__ __nv_bfloat16 g_wh[166985728], g_wl[166985728];
// dedicated split-K partial buffers for Wo/Wd
__device__ float g_part[2*Bc*Lc*Dc];

__device__ __forceinline__ uint32_t packf(float v) {
    __nv_bfloat16 h = __float2bfloat16(v);
    float hf = __bfloat162float(h);
    __nv_bfloat16 l = __float2bfloat16(v - hf);
    return (uint32_t)__bfloat16_as_ushort(h) | ((uint32_t)__bfloat16_as_ushort(l) << 16);
}
__device__ __forceinline__ void packf2(float v, __nv_bfloat16& h, __nv_bfloat16& l) {
    h = __float2bfloat16(v);
    l = __float2bfloat16(v - __bfloat162float(h));
}

__device__ __forceinline__ uint32_t smem_u32(const void* p) {
    uint32_t a;
    asm("{ .reg .u64 t; cvta.to.shared.u64 t, %1; cvt.u32.u64 %0, t; }" : "=r"(a) : "l"(p));
    return a;
}
__device__ __forceinline__ void cpasync16(uint32_t dst, const void* src) {
    asm volatile("cp.async.cg.shared.global [%0], [%1], 16;" :: "r"(dst), "l"(src) : "memory");
}
__device__ __forceinline__ void cp_commit() {
    asm volatile("cp.async.commit_group;" ::: "memory");
}
__device__ __forceinline__ void cp_wait1() {
    asm volatile("cp.async.wait_group 1;" ::: "memory");
}

// ---------------------------------------------------------------------------
// Block reductions (blockDim.x == 256)
// ---------------------------------------------------------------------------
__device__ __forceinline__ float blockReduceSum(float v) {
    __shared__ float sh[33];
    int lane = threadIdx.x & 31, wid = threadIdx.x >> 5;
    #pragma unroll
    for (int o = 16; o > 0; o >>= 1) v += __shfl_down_sync(0xffffffffu, v, o);
    if (lane == 0) sh[wid] = v;
    __syncthreads();
    v = (threadIdx.x < 8) ? sh[lane] : 0.0f;
    if (wid == 0) {
        #pragma unroll
        for (int o = 4; o > 0; o >>= 1) v += __shfl_down_sync(0xffffffffu, v, o);
        if (lane == 0) sh[32] = v;
    }
    __syncthreads();
    return sh[32];
}
__device__ __forceinline__ float blockReduceMax(float v) {
    __shared__ float sh[33];
    int lane = threadIdx.x & 31, wid = threadIdx.x >> 5;
    #pragma unroll
    for (int o = 16; o > 0; o >>= 1) v = fmaxf(v, __shfl_down_sync(0xffffffffu, v, o));
    if (lane == 0) sh[wid] = v;
    __syncthreads();
    v = (threadIdx.x < 8) ? sh[lane] : -FLT_MAX;
    if (wid == 0) {
        #pragma unroll
        for (int o = 4; o > 0; o >>= 1) v = fmaxf(v, __shfl_down_sync(0xffffffffu, v, o));
        if (lane == 0) sh[32] = v;
    }
    __syncthreads();
    return sh[32];
}

// ---------------------------------------------------------------------------
// WMMA GEMM (R10 core) + flag16 swish-fused epilogue
// ---------------------------------------------------------------------------
#define LDS_ 40

template<int BN>
__global__ __launch_bounds__(128, 2) void gemm_mma(
    const __nv_bfloat16* __restrict__ Ahp, const __nv_bfloat16* __restrict__ Alp,
    const __nv_bfloat16* __restrict__ Bhp, const __nv_bfloat16* __restrict__ Blp,
    float* __restrict__ C, __nv_bfloat16* __restrict__ Ch, __nv_bfloat16* __restrict__ Cl,
    const float* __restrict__ R,
    int K, int lda, int ldb, int ldc, int bH,
    long sAb, long sAh, long sBb, long sBh, long sCb, long sCh, int flags)
{
    const int BM = 128;
    const int WN = BN / 2;
    const int NT = WN / 16;
    const int APB = 5120;
    const int BPB = BN * LDS_;
    const int SSZ = (2 * APB + 2 * BPB) * 2;

    int by = blockIdx.y;
    if (flags & 8) by = (by < 4) ? by : 11 - by;
    int row0 = by * BM, col0 = blockIdx.x * BN;
    if ((flags & 2) && col0 >= row0 + BM) return;
    if (flags & 4) { int kc = row0 + BM; if (kc < K) K = kc; }
    int z = blockIdx.z, zb = z / bH, zh = z - zb * bH;
    long aoff = (long)zb * sAb + (long)zh * sAh;
    long boff = (long)zb * sBb + (long)zh * sBh;
    long coff = (long)zb * sCb + (long)zh * sCh;

    extern __shared__ __align__(16) char smraw[];
    uint32_t sbase = smem_u32(smraw);

    int tid = threadIdx.x, wid = tid >> 5, lane = tid & 31;
    int wm = wid & 1, wn = wid >> 1;

    wmma::fragment<wmma::accumulator, 16, 16, 16, float> acc[4][NT];
    if (R) {
        const float* Rb = R + coff;
        #pragma unroll
        for (int i = 0; i < 4; i++)
            #pragma unroll
            for (int j = 0; j < NT; j++)
                wmma::load_matrix_sync(acc[i][j],
                    Rb + (long)(row0 + wm * 64 + i * 16) * ldc + col0 + wn * WN + j * 16,
                    ldc, wmma::mem_row_major);
    } else {
        #pragma unroll
        for (int i = 0; i < 4; i++)
            #pragma unroll
            for (int j = 0; j < NT; j++)
                wmma::fill_fragment(acc[i][j], 0.0f);
    }

    const __nv_bfloat16* Ahg = Ahp + aoff + (long)row0 * lda;
    const __nv_bfloat16* Alg = Alp + aoff + (long)row0 * lda;
    const __nv_bfloat16* Bhg = Bhp + boff + (long)col0 * ldb;
    const __nv_bfloat16* Blg = Blp + boff + (long)col0 * ldb;
    int NC = K >> 5;

    auto issue = [&](int c) {
        uint32_t sb = sbase + (c & 1) * SSZ;
        int kc = c << 5;
        #pragma unroll
        for (int i = 0; i < 4; i++) {
            int lin = tid + i * 128;
            int r = lin >> 2, g = lin & 3;
            long go = (long)r * lda + kc + g * 8;
            uint32_t so = r * 80 + g * 16;
            cpasync16(sb + so, Ahg + go);
            cpasync16(sb + 2 * APB + so, Alg + go);
        }
        #pragma unroll
        for (int i = 0; i < BN / 32; i++) {
            int lin = tid + i * 128;
            int r = lin >> 2, g = lin & 3;
            long go = (long)r * ldb + kc + g * 8;
            uint32_t so = r * 80 + g * 16;
            cpasync16(sb + 4 * APB + so, Bhg + go);
            cpasync16(sb + 4 * APB + 2 * BPB + so, Blg + go);
        }
    };

    issue(0); cp_commit();
    if (NC > 1) issue(1);
    cp_commit();

    for (int c = 0; c < NC; c++) {
        cp_wait1();
        __syncthreads();
        {
            const __nv_bfloat16* base = (const __nv_bfloat16*)(smraw + (c & 1) * SSZ);
            const __nv_bfloat16* Ah = base;
            const __nv_bfloat16* Al = base + APB;
            const __nv_bfloat16* Bh = base + 2 * APB;
            const __nv_bfloat16* Bl = base + 2 * APB + BPB;
            #pragma unroll
            for (int ks = 0; ks < 2; ks++) {
                int k0 = ks * 16;
                wmma::fragment<wmma::matrix_b, 16, 16, 16, __nv_bfloat16, wmma::col_major> fbh[NT], fbl[NT];
                #pragma unroll
                for (int j = 0; j < NT; j++) {
                    wmma::load_matrix_sync(fbh[j], Bh + (wn * WN + j * 16) * LDS_ + k0, LDS_);
                    wmma::load_matrix_sync(fbl[j], Bl + (wn * WN + j * 16) * LDS_ + k0, LDS_);
                }
                #pragma unroll
                for (int i = 0; i < 4; i++) {
                    wmma::fragment<wmma::matrix_a, 16, 16, 16, __nv_bfloat16, wmma::row_major> fah, fal;
                    wmma::load_matrix_sync(fah, Ah + (wm * 64 + i * 16) * LDS_ + k0, LDS_);
                    wmma::load_matrix_sync(fal, Al + (wm * 64 + i * 16) * LDS_ + k0, LDS_);
                    #pragma unroll
                    for (int j = 0; j < NT; j++) {
                        wmma::mma_sync(acc[i][j], fah, fbh[j], acc[i][j]);
                        wmma::mma_sync(acc[i][j], fah, fbl[j], acc[i][j]);
                        wmma::mma_sync(acc[i][j], fal, fbh[j], acc[i][j]);
                    }
                }
            }
        }
        __syncthreads();
        if (c + 2 < NC) issue(c + 2);
        cp_commit();
    }

    if (flags & 16) {
        __syncthreads();
        float* st = (float*)smraw;
        #pragma unroll
        for (int i = 0; i < 4; i++)
            #pragma unroll
            for (int j = 0; j < NT; j++)
                wmma::store_matrix_sync(st + (wm * 64 + i * 16) * 132 + wn * WN + j * 16,
                                        acc[i][j], 132, wmma::mem_row_major);
        __syncthreads();
        int r = tid;
        long ob = (long)(row0 + r) * ldc + blockIdx.x * 64;
        const float* rowp = st + r * 132;
        #pragma unroll
        for (int c8 = 0; c8 < 64; c8 += 8) {
            unsigned short hb[8], lb[8];
            #pragma unroll
            for (int t = 0; t < 8; t++) {
                float gv = rowp[c8 + t];
                float pv = rowp[64 + c8 + t];
                float sw = gv / (1.0f + __expf(-gv)) * pv;
                __nv_bfloat16 hh, ll;
                packf2(sw, hh, ll);
                hb[t] = __bfloat16_as_ushort(hh);
                lb[t] = __bfloat16_as_ushort(ll);
            }
            *(uint4*)(Ch + ob + c8) = *(uint4*)hb;
            *(uint4*)(Cl + ob + c8) = *(uint4*)lb;
        }
    } else if (!Ch) {
        float* Cb = C + coff;
        #pragma unroll
        for (int i = 0; i < 4; i++)
            #pragma unroll
            for (int j = 0; j < NT; j++)
                wmma::store_matrix_sync(
                    Cb + (long)(row0 + wm * 64 + i * 16) * ldc + col0 + wn * WN + j * 16,
                    acc[i][j], ldc, wmma::mem_row_major);
    } else {
        __syncthreads();
        float* wbuf = (float*)smraw + wid * 256;
        #pragma unroll
        for (int i = 0; i < 4; i++)
            #pragma unroll
            for (int j = 0; j < NT; j++) {
                wmma::store_matrix_sync(wbuf, acc[i][j], 16, wmma::mem_row_major);
                __syncwarp();
                int r = lane >> 1, chn = lane & 1;
                const float* src = wbuf + r * 16 + chn * 8;
                __nv_bfloat16 hb[8], lb[8];
                #pragma unroll
                for (int t = 0; t < 8; t++) packf2(src[t], hb[t], lb[t]);
                long off = (long)(row0 + wm * 64 + i * 16 + r) * ldc + col0 + wn * WN + j * 16 + chn * 8 + coff;
                *(uint4*)(Ch + off) = *(uint4*)hb;
                *(uint4*)(Cl + off) = *(uint4*)lb;
                __syncwarp();
            }
    }
}

// ---------------------------------------------------------------------------
// Fused split-K reduce + residual + rmsnorm + pack
// ---------------------------------------------------------------------------
__global__ void reduce_norm_pack(float* __restrict__ y,
                                 const float* __restrict__ p0, const float* __restrict__ p1,
                                 const float* __restrict__ w,
                                 __nv_bfloat16* __restrict__ oh, __nv_bfloat16* __restrict__ ol) {
    long b = (long)blockIdx.x * Dc;
    int tid = threadIdx.x;
    float vals[4];
    float s = 0.0f;
    #pragma unroll
    for (int j = 0; j < 4; j++) {
        int i = tid + j * 256;
        float v = y[b + i] + p0[b + i] + p1[b + i];
        vals[j] = v;
        y[b + i] = v;
        s += v * v;
    }
    s = blockReduceSum(s);
    float inv = rsqrtf(s * (1.0f / Dc) + 1e-6f);
    #pragma unroll
    for (int j = 0; j < 4; j++) {
        int i = tid + j * 256;
        packf2(vals[j] * inv * w[i], oh[b + i], ol[b + i]);
    }
}

// ---------------------------------------------------------------------------
// Aux kernels
// ---------------------------------------------------------------------------
__global__ void embed_k(const int* __restrict__ tokens, const float* __restrict__ emb,
                        float* __restrict__ y) {
    int r = blockIdx.x;
    int tok = tokens[r];
    const float4* src = (const float4*)(emb + (long)tok * Dc);
    float4* dst = (float4*)(y + (long)r * Dc);
    for (int i = threadIdx.x; i < Dc / 4; i += blockDim.x) dst[i] = src[i];
}

__global__ void rmsnorm_pack(const float* __restrict__ in, const float* __restrict__ w,
                             __nv_bfloat16* __restrict__ oh, __nv_bfloat16* __restrict__ ol) {
    long b = (long)blockIdx.x * Dc;
    float s = 0.0f;
    for (int i = threadIdx.x; i < Dc; i += 256) { float v = in[b + i]; s += v * v; }
    s = blockReduceSum(s);
    float inv = rsqrtf(s * (1.0f / Dc) + 1e-6f);
    for (int i = threadIdx.x; i < Dc; i += 256)
        packf2(in[b + i] * inv * w[i], oh[b + i], ol[b + i]);
}

// RoPE reading split-K partials directly (qkv = p0 + p1 inline)
__global__ void rope_pack(const float* __restrict__ p0, const float* __restrict__ p1,
                          __nv_bfloat16* __restrict__ qh, __nv_bfloat16* __restrict__ ql,
                          __nv_bfloat16* __restrict__ kh, __nv_bfloat16* __restrict__ kl) {
    int idx = blockIdx.x * 256 + threadIdx.x;
    int i = idx & 31;
    int rest = idx >> 5;
    int h = rest & (Hc - 1);
    int rl = rest >> 4;
    int l = rl & (Lc - 1);
    float ts_inv = expf((float)i * -0.28782313662425572f);
    float ang = (float)l * ts_inv;
    float sn, cs;
    sincosf(ang, &sn, &cs);
    long src = (long)rl * 3072 + h * DHc + i;
    long dst = (long)rl * Dc + h * DHc + i;
    float q1 = p0[src] + p1[src];
    float q2 = p0[src + 32] + p1[src + 32];
    packf2((q1 * cs - q2 * sn) * 0.125f, qh[dst], ql[dst]);
    packf2((q2 * cs + q1 * sn) * 0.125f, qh[dst + 32], ql[dst + 32]);
    float k1 = p0[src + 1024] + p1[src + 1024];
    float k2 = p0[src + 1024 + 32] + p1[src + 1024 + 32];
    packf2(k1 * cs - k2 * sn, kh[dst], kl[dst]);
    packf2(k2 * cs + k1 * sn, kh[dst + 32], kl[dst + 32]);
}

// V transpose reading split-K partials directly
__global__ void vtrans_pack(const float* __restrict__ p0, const float* __restrict__ p1,
                            __nv_bfloat16* __restrict__ vh, __nv_bfloat16* __restrict__ vl) {
    __shared__ uint32_t t[32][33];
    int bh = blockIdx.z; int b = bh >> 4, h = bh & 15;
    int l0 = blockIdx.x * 32, d0 = blockIdx.y * 32;
    int tx = threadIdx.x, ty = threadIdx.y;
    long src = (long)(b * Lc + l0 + ty) * 3072 + 2048 + h * DHc + d0 + tx;
    float val = p0[src] + p1[src];
    t[ty][tx] = packf(val);
    __syncthreads();
    uint32_t p = t[tx][ty];
    long o = ((long)bh * DHc + d0 + ty) * Lc + l0 + tx;
    vh[o] = __ushort_as_bfloat16((unsigned short)(p & 0xFFFF));
    vl[o] = __ushort_as_bfloat16((unsigned short)(p >> 16));
}

__global__ void softmax_pack(const float* __restrict__ att,
                             __nv_bfloat16* __restrict__ oh, __nv_bfloat16* __restrict__ ol) {
    int qi = blockIdx.x;
    long base = ((long)blockIdx.y * Lc + qi) * Lc;
    int tid = threadIdx.x;
    float vals[4];
    float mx = -FLT_MAX;
    #pragma unroll
    for (int j = 0; j < 4; j++) {
        int kk = tid + j * 256;
        vals[j] = (kk <= qi) ? att[base + kk] : -FLT_MAX;
        mx = fmaxf(mx, vals[j]);
    }
    mx = blockReduceMax(mx);
    float s = 0.0f;
    #pragma unroll
    for (int j = 0; j < 4; j++) {
        int kk = tid + j * 256;
        if (kk <= qi) { vals[j] = __expf(vals[j] - mx); s += vals[j]; }
        else vals[j] = 0.0f;
    }
    s = blockReduceSum(s);
    float inv = 1.0f / s;
    int lim = (qi | 127) + 1;
    #pragma unroll
    for (int j = 0; j < 4; j++) {
        int kk = tid + j * 256;
        if (kk < lim) packf2(vals[j] * inv, oh[base + kk], ol[base + kk]);
    }
}

// Transpose + split-pack; ilv: 0 = plain, 1 = gate interleave, 2 = proj interleave
__global__ void wtrans(const float* __restrict__ W,
                       __nv_bfloat16* __restrict__ Oh, __nv_bfloat16* __restrict__ Ol,
                       int Kd, int Nd, long ostride, int ilv) {
    __shared__ uint32_t t[32][33];
    long li = (long)blockIdx.z * Kd * Nd;
    long lo_ = (long)blockIdx.z * ostride;
    int n0 = blockIdx.x * 32, k0 = blockIdx.y * 32;
    int tx = threadIdx.x;
    int ty = threadIdx.y;
    float4 v = *(const float4*)(W + li + (long)(k0 + ty) * Nd + n0 + tx * 4);
    t[tx * 4 + 0][ty] = packf(v.x);
    t[tx * 4 + 1][ty] = packf(v.y);
    t[tx * 4 + 2][ty] = packf(v.z);
    t[tx * 4 + 3][ty] = packf(v.w);
    __syncthreads();
    uint32_t p0 = t[ty][tx * 4], p1 = t[ty][tx * 4 + 1], p2 = t[ty][tx * 4 + 2], p3 = t[ty][tx * 4 + 3];
    ushort4 hs = make_ushort4((unsigned short)(p0 & 0xFFFF), (unsigned short)(p1 & 0xFFFF),
                              (unsigned short)(p2 & 0xFFFF), (unsigned short)(p3 & 0xFFFF));
    ushort4 ls = make_ushort4((unsigned short)(p0 >> 16), (unsigned short)(p1 >> 16),
                              (unsigned short)(p2 >> 16), (unsigned short)(p3 >> 16));
    int n = n0 + ty;
    int orow = n;
    if (ilv) orow = (n >> 6) * 128 + (n & 63) + ((ilv == 2) ? 64 : 0);
    long o = lo_ + (long)orow * Kd + k0 + tx * 4;
    *(ushort4*)(Oh + o) = hs;
    *(ushort4*)(Ol + o) = ls;
}

// ---------------------------------------------------------------------------
// Host
// ---------------------------------------------------------------------------
#define SM128 (2 * (20480 + 128 * 160))   // 81920
#define SM64  (2 * (20480 + 64 * 160))    // 61440

extern "C" void kernel_launch(void* const* d_in, const int* in_sizes, int n_in,
                              void* d_out, int out_size) {
    const int*   tokens = (const int*)d_in[0];
    const float* embed  = (const float*)d_in[1];
    const float* ln1    = (const float*)d_in[2];
    const float* Wq     = (const float*)d_in[3];
    const float* Wk     = (const float*)d_in[4];
    const float* Wv     = (const float*)d_in[5];
    const float* Wo     = (const float*)d_in[6];
    const float* ln2    = (const float*)d_in[7];
    const float* Wg     = (const float*)d_in[8];
    const float* Wp     = (const float*)d_in[9];
    const float* Wd     = (const float*)d_in[10];
    const float* out_ln = (const float*)d_in[11];
    const float* head   = (const float*)d_in[12];

    cudaFuncSetAttribute(gemm_mma<128>, cudaFuncAttributeMaxDynamicSharedMemorySize, SM128);
    cudaFuncSetAttribute(gemm_mma<64>,  cudaFuncAttributeMaxDynamicSharedMemorySize, SM64);

    float *y, *att, *part;
    __nv_bfloat16 *xh, *xl, *qh, *ql, *kh, *kl, *vth, *vtl, *th, *tl, *ph, *pl, *gh, *gl, *wh, *wl;
    cudaGetSymbolAddress((void**)&y,    g_y);
    cudaGetSymbolAddress((void**)&att,  g_att);
    cudaGetSymbolAddress((void**)&part, g_part);
    cudaGetSymbolAddress((void**)&xh,   g_xh);  cudaGetSymbolAddress((void**)&xl, g_xl);
    cudaGetSymbolAddress((void**)&qh,   g_qh);  cudaGetSymbolAddress((void**)&ql, g_ql);
    cudaGetSymbolAddress((void**)&kh,   g_kh);  cudaGetSymbolAddress((void**)&kl, g_kl);
    cudaGetSymbolAddress((void**)&vth,  g_vth); cudaGetSymbolAddress((void**)&vtl, g_vtl);
    cudaGetSymbolAddress((void**)&th,   g_th);  cudaGetSymbolAddress((void**)&tl, g_tl);
    cudaGetSymbolAddress((void**)&ph,   g_ph);  cudaGetSymbolAddress((void**)&pl, g_pl);
    cudaGetSymbolAddress((void**)&gh,   g_gh);  cudaGetSymbolAddress((void**)&gl, g_gl);
    cudaGetSymbolAddress((void**)&wh,   g_wh);  cudaGetSymbolAddress((void**)&wl, g_wl);

    const long OQKV = 0;
    const long OO   = 25165824;
    const long OGP  = 33554432;     // interleaved gate/proj
    const long OD   = 100663296;
    const long OH   = 134217728;
    const long MD   = (long)Bc * Lc * Dc;       // 2097152
    const long MQ   = (long)Bc * Lc * 3 * Dc;   // 6291456

    dim3 tw(8, 32);
    wtrans<<<dim3(32, 32, 8),   tw>>>(Wq, wh + OQKV,            wl + OQKV,            1024, 1024, 3145728, 0);
    wtrans<<<dim3(32, 32, 8),   tw>>>(Wk, wh + OQKV + 1048576,  wl + OQKV + 1048576,  1024, 1024, 3145728, 0);
    wtrans<<<dim3(32, 32, 8),   tw>>>(Wv, wh + OQKV + 2097152,  wl + OQKV + 2097152,  1024, 1024, 3145728, 0);
    wtrans<<<dim3(32, 32, 8),   tw>>>(Wo, wh + OO,              wl + OO,              1024, 1024, 1048576, 0);
    wtrans<<<dim3(128, 32, 8),  tw>>>(Wg, wh + OGP,             wl + OGP,             1024, 4096, 8388608, 1);
    wtrans<<<dim3(128, 32, 8),  tw>>>(Wp, wh + OGP,             wl + OGP,             1024, 4096, 8388608, 2);
    wtrans<<<dim3(32, 128, 8),  tw>>>(Wd, wh + OD,              wl + OD,              4096, 1024, 4194304, 0);
    wtrans<<<dim3(1000, 32, 1), tw>>>(head, wh + OH,            wl + OH,              1024, 32000, 0, 0);

    embed_k<<<Bc * Lc, 256>>>(tokens, embed, y);

    const long LL = (long)Lc * Lc;
    const long LD = (long)Lc * Dc;
    dim3 tb(32, 32);

    // initial ln1 norm for layer 0
    rmsnorm_pack<<<Bc * Lc, 256>>>(y, ln1, xh, xl);

    for (int l = 0; l < NL; l++) {
        // merged QKV with split-K=2; partials alias att, consumed directly by rope/vtrans
        gemm_mma<128><<<dim3(24, 16, 2), 128, SM128>>>(
            xh, xl, wh + OQKV + (long)l * 3145728, wl + OQKV + (long)l * 3145728,
            att, 0, 0, 0, 512, 1024, 1024, 3072, 1,
            512, 0, 512, 0, MQ, 0, 0);

        rope_pack<<<4096, 256>>>(att, att + MQ, qh, ql, kh, kl);
        vtrans_pack<<<dim3(32, 2, 32), tb>>>(att, att + MQ, vth, vtl);

        // scores (causal tiles skipped)
        gemm_mma<128><<<dim3(8, 8, 32), 128, SM128>>>(
            qh, ql, kh, kl, att, 0, 0, 0,
            64, 1024, 1024, 1024, Hc,
            LD, 64, LD, 64, (long)Hc * LL, LL, 2);

        softmax_pack<<<dim3(Lc, Bc * Hc), 256>>>(att, ph, pl);

        // AV (K clipped per M-tile), balanced row-block permutation
        gemm_mma<64><<<dim3(1, 8, 32), 128, SM64>>>(
            ph, pl, vth, vtl, 0, th, tl, 0,
            1024, 1024, 1024, 1024, Hc,
            (long)Hc * LL, LL, (long)Hc * DHc * Lc, (long)DHc * Lc, LD, 64, 4 | 8);

        // Wo split-K=2 -> partials; fused reduce + residual + ln2 norm + pack
        gemm_mma<128><<<dim3(8, 16, 2), 128, SM128>>>(
            th, tl, wh + OO + (long)l * 1048576, wl + OO + (long)l * 1048576,
            part, 0, 0, 0, 512, 1024, 1024, 1024, 1,
            512, 0, 512, 0, MD, 0, 0);
        reduce_norm_pack<<<Bc * Lc, 256>>>(y, part, part + MD, ln2 + (long)l * Dc, xh, xl);

        // merged gate+proj with fused swish epilogue (interleaved weights)
        gemm_mma<128><<<dim3(64, 16, 1), 128, SM128>>>(
            xh, xl, wh + OGP + (long)l * 8388608, wl + OGP + (long)l * 8388608,
            0, gh, gl, 0, 1024, 1024, 1024, Fc, 1, 0, 0, 0, 0, 0, 0, 16);

        // Wd split-K=2 -> partials; fused reduce + residual + next-norm + pack
        const float* wnorm = (l + 1 < NL) ? (ln1 + (long)(l + 1) * Dc) : out_ln;
        gemm_mma<128><<<dim3(8, 16, 2), 128, SM128>>>(
            gh, gl, wh + OD + (long)l * 4194304, wl + OD + (long)l * 4194304,
            part, 0, 0, 0, 2048, 4096, 4096, 1024, 1,
            2048, 0, 2048, 0, MD, 0, 0);
        reduce_norm_pack<<<Bc * Lc, 256>>>(y, part, part + MD, wnorm, xh, xl);
    }

    // head GEMM (x planes hold out_ln-normed activations)
    gemm_mma<128><<<dim3(250, 16, 1), 128, SM128>>>(
        xh, xl, wh + OH, wl + OH, (float*)d_out, 0, 0, 0,
        1024, 1024, 1024, 32000, 1, 0, 0, 0, 0, 0, 0, 0);
}